// round 1
// baseline (speedup 1.0000x reference)
#include <cuda_runtime.h>

#define SEQ   256
#define BATCH 4
#define DIM   512
#define NKV   32768
#define RQ    (SEQ * BATCH)      // 1024 query rows
#define SPLITK 16
#define KSLICE (NKV / SPLITK)    // 2048

#define BM 128
#define BN 128
#define BK 16

typedef unsigned long long u64;

// ---------------- device scratch (no allocation allowed) ----------------
__device__ float g_kproj[(size_t)NKV * DIM];      // 64 MB  _k  [N, D]
__device__ float g_vT[(size_t)DIM * NKV];         // 64 MB  _v^T [D, N]
__device__ float g_qb[RQ * DIM];                  // q transposed to [B*S, D]
__device__ float g_q[RQ * DIM];                   // projected+scaled q
__device__ float g_logits[(size_t)RQ * NKV];      // 128 MB logits / exp weights
__device__ float g_cat[RQ * 2 * DIM];             // [attn | prev_b]
__device__ float g_h[RQ * DIM];                   // gate hidden
__device__ float g_invsum[RQ];
__device__ float g_sigma[RQ];
__device__ float g_part[(size_t)SPLITK * RQ * DIM]; // split-K partials (32 MB)

// ---------------- f32x2 packed math helpers ----------------
__device__ __forceinline__ u64 pack2f(float x, float y) {
    u64 r; asm("mov.b64 %0, {%1, %2};" : "=l"(r) : "f"(x), "f"(y)); return r;
}
__device__ __forceinline__ void unpack2f(u64 v, float& x, float& y) {
    asm("mov.b64 {%0, %1}, %2;" : "=f"(x), "=f"(y) : "l"(v));
}
__device__ __forceinline__ void fma2(u64& d, u64 a, u64 b) {
    asm("fma.rn.f32x2 %0, %1, %2, %0;" : "+l"(d) : "l"(a), "l"(b));
}

// ---------------- fast exp (FMA polynomial, avoids MUFU throughput wall) ----
__device__ __forceinline__ float fast_exp(float x) {
    float t = x * 1.4426950408889634f;           // log2(e)
    t = fmaxf(t, -125.0f);
    float fi = floorf(t);
    float f  = t - fi;                            // f in [0,1)
    float p = 1.5403530393381608e-4f;             // Taylor of 2^f, deg 6
    p = fmaf(p, f, 1.3333558146428443e-3f);
    p = fmaf(p, f, 9.618129107628477e-3f);
    p = fmaf(p, f, 5.550410866482158e-2f);
    p = fmaf(p, f, 2.402265069591007e-1f);
    p = fmaf(p, f, 6.931471805599453e-1f);
    p = fmaf(p, f, 1.0f);
    int ei = (int)fi;
    float sc = __int_as_float((ei + 127) << 23);
    return p * sc;
}

// ---------------- generic tiled SGEMM: C[M,N] = A[M,K] * B[N,K]^T ----------
// bias_mode: 0 none, 1 per-col (bias[n]), 2 per-row (bias[m])
// out = relu?( ((acc + bias) * alpha) * rowscale[m] )
// If Cpart != nullptr: write raw partial for k-slice blockIdx.z (no epilogue).
__global__ __launch_bounds__(256, 2)
void sgemm_abT(const float* __restrict__ A, const float* __restrict__ B,
               float* __restrict__ C, int M, int N, int K, int ldc,
               const float* __restrict__ bias, int bias_mode,
               const float* __restrict__ rowscale,
               float alpha, int do_relu,
               float* __restrict__ Cpart, int kslice)
{
    __shared__ float As[BK][BM];
    __shared__ float Bs[BK][BN];

    const int bm = blockIdx.y * BM;
    const int bn = blockIdx.x * BN;
    const int tid = threadIdx.x;
    const int tx = tid & 15;           // 16 cols of threads
    const int ty = tid >> 4;           // 16 rows of threads

    u64 acc[8][4];
#pragma unroll
    for (int i = 0; i < 8; i++)
#pragma unroll
        for (int j = 0; j < 4; j++) acc[i][j] = 0ull;

    const int k0 = blockIdx.z * kslice;
    const int k1 = k0 + kslice;

    const int lrow = tid >> 2;          // 0..63
    const int lk   = (tid & 3) << 2;    // 0,4,8,12

    for (int kt = k0; kt < k1; kt += BK) {
        float4 a0 = *(const float4*)(A + (size_t)(bm + lrow)      * K + kt + lk);
        float4 a1 = *(const float4*)(A + (size_t)(bm + lrow + 64) * K + kt + lk);
        float4 b0 = *(const float4*)(B + (size_t)(bn + lrow)      * K + kt + lk);
        float4 b1 = *(const float4*)(B + (size_t)(bn + lrow + 64) * K + kt + lk);

        As[lk+0][lrow]    = a0.x; As[lk+1][lrow]    = a0.y;
        As[lk+2][lrow]    = a0.z; As[lk+3][lrow]    = a0.w;
        As[lk+0][lrow+64] = a1.x; As[lk+1][lrow+64] = a1.y;
        As[lk+2][lrow+64] = a1.z; As[lk+3][lrow+64] = a1.w;
        Bs[lk+0][lrow]    = b0.x; Bs[lk+1][lrow]    = b0.y;
        Bs[lk+2][lrow]    = b0.z; Bs[lk+3][lrow]    = b0.w;
        Bs[lk+0][lrow+64] = b1.x; Bs[lk+1][lrow+64] = b1.y;
        Bs[lk+2][lrow+64] = b1.z; Bs[lk+3][lrow+64] = b1.w;
        __syncthreads();

#pragma unroll
        for (int kk = 0; kk < BK; kk++) {
            u64 a2[8], b2[4];
#pragma unroll
            for (int i = 0; i < 8; i++) {
                float a = As[kk][ty * 8 + i];
                a2[i] = pack2f(a, a);
            }
            const u64* bp = (const u64*)&Bs[kk][tx * 8];
#pragma unroll
            for (int j = 0; j < 4; j++) b2[j] = bp[j];
#pragma unroll
            for (int i = 0; i < 8; i++)
#pragma unroll
                for (int j = 0; j < 4; j++) fma2(acc[i][j], a2[i], b2[j]);
        }
        __syncthreads();
    }

    const int row0 = bm + ty * 8;
    const int col0 = bn + tx * 8;

    if (Cpart) {
        float* P = Cpart + ((size_t)blockIdx.z * M + row0) * ldc + col0;
#pragma unroll
        for (int i = 0; i < 8; i++) {
            float o[8];
#pragma unroll
            for (int j = 0; j < 4; j++) unpack2f(acc[i][j], o[2*j], o[2*j+1]);
            float4* p = (float4*)(P + (size_t)i * ldc);
            p[0] = make_float4(o[0], o[1], o[2], o[3]);
            p[1] = make_float4(o[4], o[5], o[6], o[7]);
        }
        return;
    }

#pragma unroll
    for (int i = 0; i < 8; i++) {
        int row = row0 + i;
        float scale = alpha;
        if (rowscale) scale *= rowscale[row];
        float badd = (bias_mode == 2) ? bias[row] : 0.f;
        float o[8];
#pragma unroll
        for (int j = 0; j < 4; j++) unpack2f(acc[i][j], o[2*j], o[2*j+1]);
#pragma unroll
        for (int j = 0; j < 8; j++) {
            float v = o[j];
            if (bias_mode == 1) v += bias[col0 + j];
            else                v += badd;
            v *= scale;
            if (do_relu) v = fmaxf(v, 0.f);
            o[j] = v;
        }
        float4* p = (float4*)(C + (size_t)row * ldc + col0);
        p[0] = make_float4(o[0], o[1], o[2], o[3]);
        p[1] = make_float4(o[4], o[5], o[6], o[7]);
    }
}

// ---------------- prep: transpose [S,B,D] -> [B*S, D]; fill cat right half --
__global__ void prep_kernel(const float* __restrict__ q,
                            const float* __restrict__ prev,
                            float* __restrict__ qb, float* __restrict__ cat)
{
    int i = blockIdx.x * 256 + threadIdx.x;       // over SEQ*BATCH*DIM
    int d = i & (DIM - 1);
    int t = i >> 9;
    int b = t & (BATCH - 1);
    int s = t >> 2;
    int r = b * SEQ + s;
    qb[(size_t)r * DIM + d] = q[i];
    cat[(size_t)r * (2 * DIM) + DIM + d] = prev[i];
}

// ---------------- softmax over rows of logits (in place, unnormalized exp) --
__global__ void softmax_rows(float* __restrict__ logits, float* __restrict__ invsum)
{
    const int r = blockIdx.x;
    float* row = logits + (size_t)r * NKV;
    const int tid = threadIdx.x;                  // 256 threads
    __shared__ float red[8];

    float m = -1e30f;
    for (int i = tid * 4; i < NKV; i += 1024) {
        float4 v = *(const float4*)(row + i);
        m = fmaxf(m, fmaxf(fmaxf(v.x, v.y), fmaxf(v.z, v.w)));
    }
#pragma unroll
    for (int o = 16; o; o >>= 1) m = fmaxf(m, __shfl_xor_sync(0xffffffffu, m, o));
    if ((tid & 31) == 0) red[tid >> 5] = m;
    __syncthreads();
    if (tid == 0) {
        float mm = red[0];
        for (int w = 1; w < 8; w++) mm = fmaxf(mm, red[w]);
        red[0] = mm;
    }
    __syncthreads();
    m = red[0];
    __syncthreads();

    float s = 0.f;
    for (int i = tid * 4; i < NKV; i += 1024) {
        float4 v = *(const float4*)(row + i);
        v.x = fast_exp(v.x - m); v.y = fast_exp(v.y - m);
        v.z = fast_exp(v.z - m); v.w = fast_exp(v.w - m);
        s += (v.x + v.y) + (v.z + v.w);
        *(float4*)(row + i) = v;
    }
#pragma unroll
    for (int o = 16; o; o >>= 1) s += __shfl_xor_sync(0xffffffffu, s, o);
    if ((tid & 31) == 0) red[tid >> 5] = s;
    __syncthreads();
    if (tid == 0) {
        float ss = 0.f;
        for (int w = 0; w < 8; w++) ss += red[w];
        invsum[r] = 1.0f / ss;
    }
}

// ---------------- reduce split-K partials, apply 1/sum, write cat left half -
__global__ void attn_reduce(const float* __restrict__ part,
                            const float* __restrict__ invsum,
                            float* __restrict__ cat)
{
    int i = blockIdx.x * 256 + threadIdx.x;       // over RQ*DIM
    int r = i >> 9;
    int d = i & (DIM - 1);
    float s = 0.f;
#pragma unroll
    for (int z = 0; z < SPLITK; z++)
        s += part[(size_t)z * RQ * DIM + i];
    cat[(size_t)r * (2 * DIM) + d] = s * invsum[r];
}

// ---------------- sigma = sigmoid(h . Wg2 + bg2) per row --------------------
__global__ void sigma_kernel(const float* __restrict__ h,
                             const float* __restrict__ Wg2,
                             const float* __restrict__ bg2,
                             float* __restrict__ sig)
{
    const int r = blockIdx.x;
    const int tid = threadIdx.x;                  // 128 threads
    float s = 0.f;
    for (int i = tid; i < DIM; i += 128)
        s = fmaf(h[(size_t)r * DIM + i], Wg2[i], s);
#pragma unroll
    for (int o = 16; o; o >>= 1) s += __shfl_xor_sync(0xffffffffu, s, o);
    __shared__ float red[4];
    if ((tid & 31) == 0) red[tid >> 5] = s;
    __syncthreads();
    if (tid == 0) {
        float t = red[0] + red[1] + red[2] + red[3] + bg2[0];
        sig[r] = 1.0f / (1.0f + __expf(-t));
    }
}

// ---------------- final: res = attn*sig + prev*(1-sig), back to [S,B,D] -----
__global__ void final_kernel(const float* __restrict__ cat,
                             const float* __restrict__ prev,
                             const float* __restrict__ sig,
                             float* __restrict__ out)
{
    int i = blockIdx.x * 256 + threadIdx.x;       // over SEQ*BATCH*DIM
    int d = i & (DIM - 1);
    int t = i >> 9;
    int b = t & (BATCH - 1);
    int s = t >> 2;
    int r = b * SEQ + s;
    float g = sig[r];
    float a = cat[(size_t)r * (2 * DIM) + d];
    float p = prev[i];
    out[i] = fmaf(a - p, g, p);                   // a*g + p*(1-g)
}

// ---------------- launch ----------------------------------------------------
extern "C" void kernel_launch(void* const* d_in, const int* in_sizes, int n_in,
                              void* d_out, int out_size)
{
    (void)in_sizes; (void)n_in; (void)out_size;
    const float* q    = (const float*)d_in[0];
    const float* prev = (const float*)d_in[1];
    const float* Wq   = (const float*)d_in[2];
    const float* bq   = (const float*)d_in[3];
    const float* Wk   = (const float*)d_in[4];
    const float* bk   = (const float*)d_in[5];
    const float* Wv   = (const float*)d_in[6];
    const float* bv   = (const float*)d_in[7];
    const float* Wg1  = (const float*)d_in[8];
    const float* bg1  = (const float*)d_in[9];
    const float* Wg2  = (const float*)d_in[10];
    const float* bg2  = (const float*)d_in[11];
    const float* dk   = (const float*)d_in[12];
    const float* dv   = (const float*)d_in[13];
    float* out = (float*)d_out;

    float *kp, *vT, *qb, *qq, *lg, *cat, *hh, *inv, *sg, *part;
    cudaGetSymbolAddress((void**)&kp,   g_kproj);
    cudaGetSymbolAddress((void**)&vT,   g_vT);
    cudaGetSymbolAddress((void**)&qb,   g_qb);
    cudaGetSymbolAddress((void**)&qq,   g_q);
    cudaGetSymbolAddress((void**)&lg,   g_logits);
    cudaGetSymbolAddress((void**)&cat,  g_cat);
    cudaGetSymbolAddress((void**)&hh,   g_h);
    cudaGetSymbolAddress((void**)&inv,  g_invsum);
    cudaGetSymbolAddress((void**)&sg,   g_sigma);
    cudaGetSymbolAddress((void**)&part, g_part);

    const float q_alpha = 0.08838834764831845f;   // D^-0.5 / TEMP

    // layout prep
    prep_kernel<<<(SEQ*BATCH*DIM)/256, 256>>>(q, prev, qb, cat);

    // _k = dstore_k @ Wk^T + bk               [NKV, DIM]
    sgemm_abT<<<dim3(DIM/BN, NKV/BM, 1), 256>>>(dk, Wk, kp, NKV, DIM, DIM, DIM,
                                                bk, 1, nullptr, 1.f, 0, nullptr, DIM);
    // _v^T = Wv @ dstore_v^T (+ bv per row)   [DIM, NKV]
    sgemm_abT<<<dim3(NKV/BN, DIM/BM, 1), 256>>>(Wv, dv, vT, DIM, NKV, DIM, NKV,
                                                bv, 2, nullptr, 1.f, 0, nullptr, DIM);
    // _q = (qb @ Wq^T + bq) * (D^-0.5 / TEMP) [RQ, DIM]
    sgemm_abT<<<dim3(DIM/BN, RQ/BM, 1), 256>>>(qb, Wq, qq, RQ, DIM, DIM, DIM,
                                               bq, 1, nullptr, q_alpha, 0, nullptr, DIM);
    // logits = _q @ _k^T                      [RQ, NKV]
    sgemm_abT<<<dim3(NKV/BN, RQ/BM, 1), 256>>>(qq, kp, lg, RQ, NKV, DIM, NKV,
                                               nullptr, 0, nullptr, 1.f, 0, nullptr, DIM);
    // softmax rows (unnormalized exp + invsum)
    softmax_rows<<<RQ, 256>>>(lg, inv);
    // attn (split-K partials) = w @ _v        [RQ, DIM]
    sgemm_abT<<<dim3(DIM/BN, RQ/BM, SPLITK), 256>>>(lg, vT, nullptr, RQ, DIM, NKV, DIM,
                                                    nullptr, 0, nullptr, 1.f, 0, part, KSLICE);
    attn_reduce<<<(RQ*DIM)/256, 256>>>(part, inv, cat);
    // h = relu(cat @ Wg1^T + bg1)             [RQ, DIM]
    sgemm_abT<<<dim3(DIM/BN, RQ/BM, 1), 256>>>(cat, Wg1, hh, RQ, DIM, 2*DIM, DIM,
                                               bg1, 1, nullptr, 1.f, 1, nullptr, 2*DIM);
    // sigma + final blend
    sigma_kernel<<<RQ, 128>>>(hh, Wg2, bg2, sg);
    final_kernel<<<(SEQ*BATCH*DIM)/256, 256>>>(cat, prev, sg, out);
}

// round 3
// speedup vs baseline: 2.1831x; 2.1831x over previous
#include <cuda_runtime.h>
#include <cuda_bf16.h>
#include <cstdint>

#define SEQ   256
#define BATCH 4
#define DIM   512
#define NKV   32768
#define RQ    (SEQ * BATCH)          // 1024
#define ASPLIT 8
#define AKSLICE (NKV / ASPLIT)       // 4096

typedef unsigned int u32;
typedef unsigned long long u64;
typedef __nv_bfloat16 bf16;
typedef __nv_bfloat162 bf162;

// ======================= device scratch ====================================
__device__ __align__(16) bf16 g_dkh[NKV * DIM], g_dkl[NKV * DIM];
__device__ __align__(16) bf16 g_dvh[NKV * DIM], g_dvl[NKV * DIM];
__device__ __align__(16) bf16 g_kh [NKV * DIM], g_kl [NKV * DIM];
__device__ __align__(16) bf16 g_vth[NKV * DIM], g_vtl[NKV * DIM];   // [DIM,NKV]
__device__ __align__(16) bf16 g_qbh[RQ * DIM],  g_qbl[RQ * DIM];
__device__ __align__(16) bf16 g_qh [RQ * DIM],  g_ql [RQ * DIM];
__device__ __align__(16) bf16 g_wqh[DIM * DIM], g_wql[DIM * DIM];
__device__ __align__(16) bf16 g_wkh[DIM * DIM], g_wkl[DIM * DIM];
__device__ __align__(16) bf16 g_wvh[DIM * DIM], g_wvl[DIM * DIM];
__device__ __align__(16) bf16 g_g1h[DIM * 2 * DIM], g_g1l[DIM * 2 * DIM];
__device__ __align__(16) float g_logits[(size_t)RQ * NKV];          // 128 MB
__device__ __align__(16) bf16 g_wh[(size_t)RQ * NKV], g_wl[(size_t)RQ * NKV];
__device__ __align__(16) bf16 g_cath[RQ * 2 * DIM], g_catl[RQ * 2 * DIM];
__device__ __align__(16) float g_hbuf[RQ * DIM];
__device__ __align__(16) float g_attn[RQ * DIM];
__device__ float g_invsum[RQ];
__device__ float g_sigma[RQ];
__device__ __align__(16) float g_part[(size_t)ASPLIT * RQ * DIM];

// ======================= PTX helpers =======================================
__device__ __forceinline__ u32 smem_u32(const void* p) {
    u32 a;
    asm("{ .reg .u64 t; cvta.to.shared.u64 t, %1; cvt.u32.u64 %0, t; }"
        : "=r"(a) : "l"(p));
    return a;
}

#define CP_ASYNC16(dst, src) \
    asm volatile("cp.async.cg.shared.global [%0], [%1], 16;" :: "r"(dst), "l"(src))
#define CP_COMMIT() asm volatile("cp.async.commit_group;" ::: "memory")
#define CP_WAIT(n)  asm volatile("cp.async.wait_group %0;" :: "n"(n) : "memory")

#define LDMX4(r, addr) \
    asm volatile("ldmatrix.sync.aligned.m8n8.x4.shared.b16 {%0,%1,%2,%3}, [%4];" \
        : "=r"((r)[0]), "=r"((r)[1]), "=r"((r)[2]), "=r"((r)[3]) : "r"(addr))

#define MMA_BF16(d, a, b) \
    asm volatile("mma.sync.aligned.m16n8k16.row.col.f32.bf16.bf16.f32 " \
        "{%0,%1,%2,%3}, {%4,%5,%6,%7}, {%8,%9}, {%0,%1,%2,%3};" \
        : "+f"((d)[0]), "+f"((d)[1]), "+f"((d)[2]), "+f"((d)[3]) \
        : "r"((a)[0]), "r"((a)[1]), "r"((a)[2]), "r"((a)[3]), \
          "r"((b)[0]), "r"((b)[1]))

__device__ __forceinline__ void bsplit(float v, bf16& h, bf16& l) {
    h = __float2bfloat16(v);
    l = __float2bfloat16(v - __bfloat162float(h));
}

// ======================= pipelined HMMA split-bf16 GEMM ====================
// C[M,N] = (Ah+Al)[M,K] * (Bh+Bl)[N,K]^T  (ll term dropped)
// out_mode 0: fp32 C (+ split-K offset z*strideZ); out_mode 1: bf16 hi/lo pair
// bias_mode: 0 none, 1 per-col bias[n], 2 per-row bias[m]
#define GKC 32
#define SROW 80                    // bytes per smem row (64 data + 16 pad)
#define TILE_B 10240               // 128 rows * 80B
#define STG_B (4 * TILE_B)         // Ah, Al, Bh, Bl
#define GSMEM (3 * STG_B)          // 122880

__global__ __launch_bounds__(256, 1)
void gemm_bf16s(const bf16* __restrict__ Ah, const bf16* __restrict__ Al,
                const bf16* __restrict__ Bh, const bf16* __restrict__ Bl,
                float* __restrict__ Cf, bf16* __restrict__ Chi, bf16* __restrict__ Clo,
                int lda, int ldb, int ldc, int kslice,
                const float* __restrict__ bias, int bias_mode,
                float alpha, int do_relu, int swap, int out_mode, long long strideZ)
{
    extern __shared__ char smem[];
    const u32 sb = smem_u32(smem);
    const int tid = threadIdx.x;
    const int lane = tid & 31, wid = tid >> 5;
    const int wm = wid >> 1, wn = wid & 1;          // 4x2 warp grid
    const int mtile = swap ? blockIdx.x : blockIdx.y;
    const int ntile = swap ? blockIdx.y : blockIdx.x;
    const int z = blockIdx.z;
    const long long kbase = (long long)z * kslice;
    const int NC = kslice / GKC;

    auto load_stage = [&](int c) {
        const u32 st = sb + (u32)(c % 3) * STG_B;
        const long long kb = kbase + (long long)c * GKC;
#pragma unroll
        for (int i = 0; i < 2; i++) {
            const int idx = tid + i * 256;           // 0..511
            const int row = idx >> 2, ch = idx & 3;
            const u32 so = (u32)(row * SROW + ch * 16);
            const long long aoff = (long long)(mtile * 128 + row) * lda + kb + ch * 8;
            const long long boff = (long long)(ntile * 128 + row) * ldb + kb + ch * 8;
            CP_ASYNC16(st + so,              (const char*)(Ah + aoff));
            CP_ASYNC16(st + TILE_B + so,     (const char*)(Al + aoff));
            CP_ASYNC16(st + 2 * TILE_B + so, (const char*)(Bh + boff));
            CP_ASYNC16(st + 3 * TILE_B + so, (const char*)(Bl + boff));
        }
        CP_COMMIT();
    };

    float acc[2][8][4];
#pragma unroll
    for (int mt = 0; mt < 2; mt++)
#pragma unroll
        for (int nt = 0; nt < 8; nt++)
#pragma unroll
            for (int j = 0; j < 4; j++) acc[mt][nt][j] = 0.f;

    load_stage(0);
    load_stage(1);

    // ldmatrix lane addressing (element units)
    const u32 a_row = (u32)(wm * 32 + (lane & 15));
    const u32 a_ke  = (u32)((lane >> 4) * 8);
    const u32 b_row = (u32)(wn * 64 + ((lane >> 4) << 3) + (lane & 7));
    const u32 b_ke  = (u32)(((lane >> 3) & 1) * 8);

    for (int c = 0; c < NC; c++) {
        if (c + 1 < NC) { CP_WAIT(1); } else { CP_WAIT(0); }
        __syncthreads();
        if (c + 2 < NC) load_stage(c + 2);

        const u32 st = sb + (u32)(c % 3) * STG_B;
#pragma unroll
        for (int ks = 0; ks < 2; ks++) {
            const u32 k0 = ks * 16;
            u32 ah[2][4], al[2][4], bh[8][2], bl[8][2];
#pragma unroll
            for (int mt = 0; mt < 2; mt++) {
                const u32 addr = st + (a_row + mt * 16) * SROW + (k0 + a_ke) * 2;
                LDMX4(ah[mt], addr);
                LDMX4(al[mt], addr + TILE_B);
            }
#pragma unroll
            for (int nt2 = 0; nt2 < 4; nt2++) {
                const u32 addr = st + 2 * TILE_B + (b_row + nt2 * 16) * SROW + (k0 + b_ke) * 2;
                u32 r[4];
                LDMX4(r, addr);
                bh[2 * nt2][0] = r[0]; bh[2 * nt2][1] = r[1];
                bh[2 * nt2 + 1][0] = r[2]; bh[2 * nt2 + 1][1] = r[3];
                LDMX4(r, addr + TILE_B);
                bl[2 * nt2][0] = r[0]; bl[2 * nt2][1] = r[1];
                bl[2 * nt2 + 1][0] = r[2]; bl[2 * nt2 + 1][1] = r[3];
            }
#pragma unroll
            for (int mt = 0; mt < 2; mt++)
#pragma unroll
                for (int nt = 0; nt < 8; nt++) {
                    MMA_BF16(acc[mt][nt], ah[mt], bh[nt]);
                    MMA_BF16(acc[mt][nt], ah[mt], bl[nt]);
                    MMA_BF16(acc[mt][nt], al[mt], bh[nt]);
                }
        }
    }

    // ---------------- epilogue: stage fp32 tile in smem, coalesced out -----
    __syncthreads();
    float* stage = (float*)smem;                    // [128][132]
    const int l4 = lane >> 2, l2 = (lane & 3) * 2;

#pragma unroll
    for (int mt = 0; mt < 2; mt++) {
        const int lr = wm * 32 + mt * 16 + l4;
        const int grow = mtile * 128 + lr;
        float br0 = 0.f, br1 = 0.f;
        if (bias_mode == 2) { br0 = bias[grow]; br1 = bias[grow + 8]; }
#pragma unroll
        for (int nt = 0; nt < 8; nt++) {
            const int lc = wn * 64 + nt * 8 + l2;
            float bc0 = 0.f, bc1 = 0.f;
            if (bias_mode == 1) {
                bc0 = bias[ntile * 128 + lc];
                bc1 = bias[ntile * 128 + lc + 1];
            }
            float v0 = (acc[mt][nt][0] + bc0 + br0) * alpha;
            float v1 = (acc[mt][nt][1] + bc1 + br0) * alpha;
            float v2 = (acc[mt][nt][2] + bc0 + br1) * alpha;
            float v3 = (acc[mt][nt][3] + bc1 + br1) * alpha;
            if (do_relu) {
                v0 = fmaxf(v0, 0.f); v1 = fmaxf(v1, 0.f);
                v2 = fmaxf(v2, 0.f); v3 = fmaxf(v3, 0.f);
            }
            stage[lr * 132 + lc] = v0;
            stage[lr * 132 + lc + 1] = v1;
            stage[(lr + 8) * 132 + lc] = v2;
            stage[(lr + 8) * 132 + lc + 1] = v3;
        }
    }
    __syncthreads();

    if (out_mode == 0) {
        float* Cp = Cf + (long long)z * strideZ
                  + (long long)(mtile * 128) * ldc + ntile * 128;
#pragma unroll
        for (int i = 0; i < 16; i++) {
            const int idx = tid + i * 256;           // 0..4095
            const int rr = idx >> 5, c4 = (idx & 31) * 4;
            float4 v = *(float4*)&stage[rr * 132 + c4];
            *(float4*)(Cp + (long long)rr * ldc + c4) = v;
        }
    } else {
        bf16* Hp = Chi + (long long)(mtile * 128) * ldc + ntile * 128;
        bf16* Lp = Clo + (long long)(mtile * 128) * ldc + ntile * 128;
#pragma unroll
        for (int i = 0; i < 16; i++) {
            const int idx = tid + i * 256;
            const int rr = idx >> 5, c4 = (idx & 31) * 4;
            float4 v = *(float4*)&stage[rr * 132 + c4];
            bf16 h0, h1, h2, h3, l0, l1, l2b, l3;
            bsplit(v.x, h0, l0); bsplit(v.y, h1, l1);
            bsplit(v.z, h2, l2b); bsplit(v.w, h3, l3);
            bf162 hp0; hp0.x = h0; hp0.y = h1;
            bf162 hp1; hp1.x = h2; hp1.y = h3;
            bf162 lp0; lp0.x = l0; lp0.y = l1;
            bf162 lp1; lp1.x = l2b; lp1.y = l3;
            bf162* hq = (bf162*)(Hp + (long long)rr * ldc + c4);
            bf162* lq = (bf162*)(Lp + (long long)rr * ldc + c4);
            hq[0] = hp0; hq[1] = hp1;
            lq[0] = lp0; lq[1] = lp1;
        }
    }
}

// ======================= elementwise kernels ===============================
__global__ void split4(const float4* __restrict__ x, bf162* __restrict__ h,
                       bf162* __restrict__ l, int n4)
{
    int i = blockIdx.x * 256 + threadIdx.x;
    if (i >= n4) return;
    float4 v = x[i];
    bf16 h0, h1, h2, h3, l0, l1, l2, l3;
    bsplit(v.x, h0, l0); bsplit(v.y, h1, l1);
    bsplit(v.z, h2, l2); bsplit(v.w, h3, l3);
    bf162 a; a.x = h0; a.y = h1;
    bf162 b; b.x = h2; b.y = h3;
    bf162 c; c.x = l0; c.y = l1;
    bf162 d; d.x = l2; d.y = l3;
    h[2 * i] = a; h[2 * i + 1] = b;
    l[2 * i] = c; l[2 * i + 1] = d;
}

__global__ void prep_kernel(const float* __restrict__ q, const float* __restrict__ prev,
                            bf16* __restrict__ qbh, bf16* __restrict__ qbl,
                            bf16* __restrict__ cath, bf16* __restrict__ catl)
{
    int i = blockIdx.x * 256 + threadIdx.x;     // SEQ*BATCH*DIM
    int d = i & (DIM - 1);
    int t = i >> 9;
    int b = t & (BATCH - 1);
    int s = t >> 2;
    int r = b * SEQ + s;
    bf16 h, l;
    bsplit(q[i], h, l);
    qbh[(size_t)r * DIM + d] = h; qbl[(size_t)r * DIM + d] = l;
    bsplit(prev[i], h, l);
    cath[(size_t)r * 2 * DIM + DIM + d] = h;
    catl[(size_t)r * 2 * DIM + DIM + d] = l;
}

__device__ __forceinline__ float fast_exp(float x) {
    float t = x * 1.4426950408889634f;
    t = fmaxf(t, -125.0f);
    float fi = floorf(t);
    float f = t - fi;
    float p = 1.5403530393381608e-4f;
    p = fmaf(p, f, 1.3333558146428443e-3f);
    p = fmaf(p, f, 9.618129107628477e-3f);
    p = fmaf(p, f, 5.550410866482158e-2f);
    p = fmaf(p, f, 2.402265069591007e-1f);
    p = fmaf(p, f, 6.931471805599453e-1f);
    p = fmaf(p, f, 1.0f);
    return p * __int_as_float(((int)fi + 127) << 23);
}

__global__ void softmax_rows(const float* __restrict__ logits,
                             bf162* __restrict__ wh, bf162* __restrict__ wl,
                             float* __restrict__ invsum)
{
    const int r = blockIdx.x;
    const float* row = logits + (size_t)r * NKV;
    const int tid = threadIdx.x;               // 256
    __shared__ float red[8];

    float m = -1e30f;
    for (int i = tid * 4; i < NKV; i += 1024) {
        float4 v = *(const float4*)(row + i);
        m = fmaxf(m, fmaxf(fmaxf(v.x, v.y), fmaxf(v.z, v.w)));
    }
#pragma unroll
    for (int o = 16; o; o >>= 1) m = fmaxf(m, __shfl_xor_sync(0xffffffffu, m, o));
    if ((tid & 31) == 0) red[tid >> 5] = m;
    __syncthreads();
    if (tid == 0) {
        float mm = red[0];
        for (int w = 1; w < 8; w++) mm = fmaxf(mm, red[w]);
        red[0] = mm;
    }
    __syncthreads();
    m = red[0];
    __syncthreads();

    float s = 0.f;
    for (int i = tid * 4; i < NKV; i += 1024) {
        float4 v = *(const float4*)(row + i);
        float e0 = fast_exp(v.x - m), e1 = fast_exp(v.y - m);
        float e2 = fast_exp(v.z - m), e3 = fast_exp(v.w - m);
        s += (e0 + e1) + (e2 + e3);
        bf16 h0, h1, h2, h3, l0, l1, l2, l3;
        bsplit(e0, h0, l0); bsplit(e1, h1, l1);
        bsplit(e2, h2, l2); bsplit(e3, h3, l3);
        bf162 a; a.x = h0; a.y = h1;
        bf162 b; b.x = h2; b.y = h3;
        bf162 c; c.x = l0; c.y = l1;
        bf162 d; d.x = l2; d.y = l3;
        size_t o2 = ((size_t)r * NKV + i) >> 1;
        wh[o2] = a; wh[o2 + 1] = b;
        wl[o2] = c; wl[o2 + 1] = d;
    }
#pragma unroll
    for (int o = 16; o; o >>= 1) s += __shfl_xor_sync(0xffffffffu, s, o);
    if ((tid & 31) == 0) red[tid >> 5] = s;
    __syncthreads();
    if (tid == 0) {
        float ss = 0.f;
        for (int w = 0; w < 8; w++) ss += red[w];
        invsum[r] = 1.0f / ss;
    }
}

__global__ void attn_reduce(const float* __restrict__ part, const float* __restrict__ invsum,
                            float* __restrict__ attn,
                            bf16* __restrict__ cath, bf16* __restrict__ catl)
{
    int i = blockIdx.x * 256 + threadIdx.x;     // RQ*DIM
    int r = i >> 9;
    int d = i & (DIM - 1);
    float s = 0.f;
#pragma unroll
    for (int z = 0; z < ASPLIT; z++) s += part[(size_t)z * RQ * DIM + i];
    float v = s * invsum[r];
    attn[i] = v;
    bf16 h, l;
    bsplit(v, h, l);
    cath[(size_t)r * 2 * DIM + d] = h;
    catl[(size_t)r * 2 * DIM + d] = l;
}

__global__ void sigma_kernel(const float* __restrict__ h, const float* __restrict__ Wg2,
                             const float* __restrict__ bg2, float* __restrict__ sig)
{
    const int r = blockIdx.x;
    const int tid = threadIdx.x;               // 128
    float s = 0.f;
    for (int i = tid; i < DIM; i += 128)
        s = fmaf(h[(size_t)r * DIM + i], Wg2[i], s);
#pragma unroll
    for (int o = 16; o; o >>= 1) s += __shfl_xor_sync(0xffffffffu, s, o);
    __shared__ float red[4];
    if ((tid & 31) == 0) red[tid >> 5] = s;
    __syncthreads();
    if (tid == 0) {
        float t = red[0] + red[1] + red[2] + red[3] + bg2[0];
        sig[r] = 1.0f / (1.0f + __expf(-t));
    }
}

__global__ void final_kernel(const float* __restrict__ attn, const float* __restrict__ prev,
                             const float* __restrict__ sig, float* __restrict__ out)
{
    int i = blockIdx.x * 256 + threadIdx.x;     // SEQ*BATCH*DIM
    int d = i & (DIM - 1);
    int t = i >> 9;
    int b = t & (BATCH - 1);
    int s = t >> 2;
    int r = b * SEQ + s;
    float g = sig[r];
    float a = attn[(size_t)r * DIM + d];
    float p = prev[i];
    out[i] = fmaf(a - p, g, p);
}

// ======================= launch =============================================
extern "C" void kernel_launch(void* const* d_in, const int* in_sizes, int n_in,
                              void* d_out, int out_size)
{
    (void)in_sizes; (void)n_in; (void)out_size;
    const float* q    = (const float*)d_in[0];
    const float* prev = (const float*)d_in[1];
    const float* Wq   = (const float*)d_in[2];
    const float* bq   = (const float*)d_in[3];
    const float* Wk   = (const float*)d_in[4];
    const float* bk   = (const float*)d_in[5];
    const float* Wv   = (const float*)d_in[6];
    const float* bv   = (const float*)d_in[7];
    const float* Wg1  = (const float*)d_in[8];
    const float* bg1  = (const float*)d_in[9];
    const float* Wg2  = (const float*)d_in[10];
    const float* bg2  = (const float*)d_in[11];
    const float* dk   = (const float*)d_in[12];
    const float* dv   = (const float*)d_in[13];
    float* out = (float*)d_out;

    static int smem_set = 0;
    if (!smem_set) {
        cudaFuncSetAttribute(gemm_bf16s, cudaFuncAttributeMaxDynamicSharedMemorySize, GSMEM);
        smem_set = 1;
    }

    bf16 *dkh, *dkl, *dvh, *dvl, *kh, *kl, *vth, *vtl, *qbh, *qbl, *qh, *ql;
    bf16 *wqh, *wql, *wkh, *wkl, *wvh, *wvl, *g1h, *g1l, *wh, *wl, *cath, *catl;
    float *lg, *hbuf, *attn, *inv, *sg, *part;
    cudaGetSymbolAddress((void**)&dkh, g_dkh);  cudaGetSymbolAddress((void**)&dkl, g_dkl);
    cudaGetSymbolAddress((void**)&dvh, g_dvh);  cudaGetSymbolAddress((void**)&dvl, g_dvl);
    cudaGetSymbolAddress((void**)&kh,  g_kh);   cudaGetSymbolAddress((void**)&kl,  g_kl);
    cudaGetSymbolAddress((void**)&vth, g_vth);  cudaGetSymbolAddress((void**)&vtl, g_vtl);
    cudaGetSymbolAddress((void**)&qbh, g_qbh);  cudaGetSymbolAddress((void**)&qbl, g_qbl);
    cudaGetSymbolAddress((void**)&qh,  g_qh);   cudaGetSymbolAddress((void**)&ql,  g_ql);
    cudaGetSymbolAddress((void**)&wqh, g_wqh);  cudaGetSymbolAddress((void**)&wql, g_wql);
    cudaGetSymbolAddress((void**)&wkh, g_wkh);  cudaGetSymbolAddress((void**)&wkl, g_wkl);
    cudaGetSymbolAddress((void**)&wvh, g_wvh);  cudaGetSymbolAddress((void**)&wvl, g_wvl);
    cudaGetSymbolAddress((void**)&g1h, g_g1h);  cudaGetSymbolAddress((void**)&g1l, g_g1l);
    cudaGetSymbolAddress((void**)&wh,  g_wh);   cudaGetSymbolAddress((void**)&wl,  g_wl);
    cudaGetSymbolAddress((void**)&cath, g_cath); cudaGetSymbolAddress((void**)&catl, g_catl);
    cudaGetSymbolAddress((void**)&lg,  g_logits);
    cudaGetSymbolAddress((void**)&hbuf, g_hbuf);
    cudaGetSymbolAddress((void**)&attn, g_attn);
    cudaGetSymbolAddress((void**)&inv, g_invsum);
    cudaGetSymbolAddress((void**)&sg,  g_sigma);
    cudaGetSymbolAddress((void**)&part, g_part);

    const float q_alpha = 0.08838834764831845f;   // D^-0.5 / TEMP

    // --- input conversions ---
    split4<<<(NKV * DIM / 4) / 256, 256>>>((const float4*)dk, (bf162*)dkh, (bf162*)dkl, NKV * DIM / 4);
    split4<<<(NKV * DIM / 4) / 256, 256>>>((const float4*)dv, (bf162*)dvh, (bf162*)dvl, NKV * DIM / 4);
    split4<<<(DIM * DIM / 4) / 256, 256>>>((const float4*)Wq, (bf162*)wqh, (bf162*)wql, DIM * DIM / 4);
    split4<<<(DIM * DIM / 4) / 256, 256>>>((const float4*)Wk, (bf162*)wkh, (bf162*)wkl, DIM * DIM / 4);
    split4<<<(DIM * DIM / 4) / 256, 256>>>((const float4*)Wv, (bf162*)wvh, (bf162*)wvl, DIM * DIM / 4);
    split4<<<(DIM * 2 * DIM / 4) / 256, 256>>>((const float4*)Wg1, (bf162*)g1h, (bf162*)g1l, DIM * 2 * DIM / 4);
    prep_kernel<<<(SEQ * BATCH * DIM) / 256, 256>>>(q, prev, qbh, qbl, cath, catl);

    // --- K projection: [NKV,DIM] = dk @ Wk^T + bk  -> bf16 pair ---
    gemm_bf16s<<<dim3(DIM / 128, NKV / 128, 1), 256, GSMEM>>>(
        dkh, dkl, wkh, wkl, nullptr, kh, kl,
        DIM, DIM, DIM, DIM, bk, 1, 1.f, 0, 0, 1, 0);

    // --- V^T projection: [DIM,NKV] = Wv @ dv^T (+bv per row) -> bf16 pair ---
    gemm_bf16s<<<dim3(DIM / 128, NKV / 128, 1), 256, GSMEM>>>(
        wvh, wvl, dvh, dvl, nullptr, vth, vtl,
        DIM, DIM, NKV, DIM, bv, 2, 1.f, 0, 1, 1, 0);

    // --- Q projection: [RQ,DIM] = (qb @ Wq^T + bq) * alpha -> bf16 pair ---
    gemm_bf16s<<<dim3(DIM / 128, RQ / 128, 1), 256, GSMEM>>>(
        qbh, qbl, wqh, wql, nullptr, qh, ql,
        DIM, DIM, DIM, DIM, bq, 1, q_alpha, 0, 0, 1, 0);

    // --- logits: [RQ,NKV] = q @ k^T -> fp32  (x = mtile so K-tiles shared) ---
    gemm_bf16s<<<dim3(RQ / 128, NKV / 128, 1), 256, GSMEM>>>(
        qh, ql, kh, kl, lg, nullptr, nullptr,
        DIM, DIM, NKV, DIM, nullptr, 0, 1.f, 0, 1, 0, 0);

    // --- softmax -> unnormalized exp bf16 pair + invsum ---
    softmax_rows<<<RQ, 256>>>(lg, (bf162*)wh, (bf162*)wl, inv);

    // --- attn split-K: part[z] = w @ vT over K-slices -> fp32 partials ---
    gemm_bf16s<<<dim3(DIM / 128, RQ / 128, ASPLIT), 256, GSMEM>>>(
        wh, wl, vth, vtl, part, nullptr, nullptr,
        NKV, NKV, DIM, AKSLICE, nullptr, 0, 1.f, 0, 0, 0, (long long)RQ * DIM);

    attn_reduce<<<(RQ * DIM) / 256, 256>>>(part, inv, attn, cath, catl);

    // --- gate: h = relu(cat @ Wg1^T + bg1) -> fp32 ---
    gemm_bf16s<<<dim3(DIM / 128, RQ / 128, 1), 256, GSMEM>>>(
        cath, catl, g1h, g1l, hbuf, nullptr, nullptr,
        2 * DIM, 2 * DIM, DIM, 2 * DIM, bg1, 1, 1.f, 1, 0, 0, 0);

    sigma_kernel<<<RQ, 128>>>(hbuf, Wg2, bg2, sg);
    final_kernel<<<(SEQ * BATCH * DIM) / 256, 256>>>(attn, prev, sg, out);
}

// round 4
// speedup vs baseline: 4.6013x; 2.1077x over previous
#include <cuda_runtime.h>
#include <cuda_fp16.h>
#include <cstdint>

#define SEQ   256
#define BATCH 4
#define DIM   512
#define NKV   32768
#define RQ    (SEQ * BATCH)          // 1024
#define ASPLIT 8
#define AKSLICE (NKV / ASPLIT)       // 4096

typedef unsigned int u32;
typedef __half fp16;

// ======================= device scratch ====================================
__device__ __align__(16) fp16 g_dkh[NKV * DIM];
__device__ __align__(16) fp16 g_dvh[NKV * DIM];
__device__ __align__(16) fp16 g_kh [NKV * DIM];
__device__ __align__(16) fp16 g_vth[NKV * DIM];      // [DIM,NKV]
__device__ __align__(16) fp16 g_qbh[RQ * DIM];
__device__ __align__(16) fp16 g_qh [RQ * DIM];
__device__ __align__(16) fp16 g_wqh[DIM * DIM];
__device__ __align__(16) fp16 g_wkh[DIM * DIM];
__device__ __align__(16) fp16 g_wvh[DIM * DIM];
__device__ __align__(16) fp16 g_g1h[DIM * 2 * DIM];
__device__ __align__(16) float g_logits[(size_t)RQ * NKV];   // 128 MB
__device__ __align__(16) fp16 g_wh[(size_t)RQ * NKV];        // 64 MB
__device__ __align__(16) fp16 g_cath[RQ * 2 * DIM];
__device__ __align__(16) float g_hbuf[RQ * DIM];
__device__ __align__(16) float g_attn[RQ * DIM];
__device__ float g_invsum[RQ];
__device__ float g_sigma[RQ];
__device__ __align__(16) float g_part[(size_t)ASPLIT * RQ * DIM];

// ======================= PTX helpers =======================================
__device__ __forceinline__ u32 smem_u32(const void* p) {
    u32 a;
    asm("{ .reg .u64 t; cvta.to.shared.u64 t, %1; cvt.u32.u64 %0, t; }"
        : "=r"(a) : "l"(p));
    return a;
}

#define CP_ASYNC16(dst, src) \
    asm volatile("cp.async.cg.shared.global [%0], [%1], 16;" :: "r"(dst), "l"(src))
#define CP_COMMIT() asm volatile("cp.async.commit_group;" ::: "memory")
#define CP_WAIT(n)  asm volatile("cp.async.wait_group %0;" :: "n"(n) : "memory")

#define LDMX4(r, addr) \
    asm volatile("ldmatrix.sync.aligned.m8n8.x4.shared.b16 {%0,%1,%2,%3}, [%4];" \
        : "=r"((r)[0]), "=r"((r)[1]), "=r"((r)[2]), "=r"((r)[3]) : "r"(addr))

#define MMA_F16(d, a, b) \
    asm volatile("mma.sync.aligned.m16n8k16.row.col.f32.f16.f16.f32 " \
        "{%0,%1,%2,%3}, {%4,%5,%6,%7}, {%8,%9}, {%0,%1,%2,%3};" \
        : "+f"((d)[0]), "+f"((d)[1]), "+f"((d)[2]), "+f"((d)[3]) \
        : "r"((a)[0]), "r"((a)[1]), "r"((a)[2]), "r"((a)[3]), \
          "r"((b)[0]), "r"((b)[1]))

// ======================= pipelined HMMA fp16 GEMM ==========================
// C[M,N] = A[M,K] * B[N,K]^T, fp16 in, fp32 accumulate
// out_mode 0: fp32 C (+ split-K offset z*strideZ); out_mode 1: fp16 C
// bias_mode: 0 none, 1 per-col bias[n], 2 per-row bias[m]
#define GKC 64
#define SROW 144                   // bytes per smem row (128 data + 16 pad)
#define TILE_B (128 * SROW)        // 18432
#define STG_B (2 * TILE_B)         // A + B
#define GSMEM (3 * STG_B)          // 110592

__global__ __launch_bounds__(256, 1)
void gemm_f16(const fp16* __restrict__ A, const fp16* __restrict__ B,
              float* __restrict__ Cf, fp16* __restrict__ Ch,
              int lda, int ldb, int ldc, int kslice,
              const float* __restrict__ bias, int bias_mode,
              float alpha, int do_relu, int swap, int out_mode, long long strideZ)
{
    extern __shared__ char smem[];
    const u32 sb = smem_u32(smem);
    const int tid = threadIdx.x;
    const int lane = tid & 31, wid = tid >> 5;
    const int wm = wid >> 1, wn = wid & 1;          // 4x2 warp grid
    const int mtile = swap ? blockIdx.x : blockIdx.y;
    const int ntile = swap ? blockIdx.y : blockIdx.x;
    const int z = blockIdx.z;
    const long long kbase = (long long)z * kslice;
    const int NC = kslice / GKC;

    auto load_stage = [&](int c) {
        const u32 st = sb + (u32)(c % 3) * STG_B;
        const long long kb = kbase + (long long)c * GKC;
#pragma unroll
        for (int i = 0; i < 4; i++) {               // A tile: 128 rows x 128B
            const int idx = tid + i * 256;           // 0..1023
            const int row = idx >> 3, ch = idx & 7;
            const u32 so = (u32)(row * SROW + ch * 16);
            const long long aoff = (long long)(mtile * 128 + row) * lda + kb + ch * 8;
            CP_ASYNC16(st + so, (const char*)(A + aoff));
        }
#pragma unroll
        for (int i = 0; i < 4; i++) {               // B tile
            const int idx = tid + i * 256;
            const int row = idx >> 3, ch = idx & 7;
            const u32 so = (u32)(row * SROW + ch * 16);
            const long long boff = (long long)(ntile * 128 + row) * ldb + kb + ch * 8;
            CP_ASYNC16(st + TILE_B + so, (const char*)(B + boff));
        }
        CP_COMMIT();
    };

    float acc[2][8][4];
#pragma unroll
    for (int mt = 0; mt < 2; mt++)
#pragma unroll
        for (int nt = 0; nt < 8; nt++)
#pragma unroll
            for (int j = 0; j < 4; j++) acc[mt][nt][j] = 0.f;

    load_stage(0);
    load_stage(1);

    // ldmatrix lane addressing (element units)
    const u32 a_row = (u32)(wm * 32 + (lane & 15));
    const u32 a_ke  = (u32)((lane >> 4) * 8);
    const u32 b_row = (u32)(wn * 64 + ((lane >> 4) << 3) + (lane & 7));
    const u32 b_ke  = (u32)(((lane >> 3) & 1) * 8);

    for (int c = 0; c < NC; c++) {
        if (c + 1 < NC) { CP_WAIT(1); } else { CP_WAIT(0); }
        __syncthreads();
        if (c + 2 < NC) load_stage(c + 2);

        const u32 st = sb + (u32)(c % 3) * STG_B;
#pragma unroll
        for (int ks = 0; ks < 4; ks++) {
            const u32 k0 = ks * 16;
            u32 af[2][4], bf[8][2];
#pragma unroll
            for (int mt = 0; mt < 2; mt++) {
                const u32 addr = st + (a_row + mt * 16) * SROW + (k0 + a_ke) * 2;
                LDMX4(af[mt], addr);
            }
#pragma unroll
            for (int nt2 = 0; nt2 < 4; nt2++) {
                const u32 addr = st + TILE_B + (b_row + nt2 * 16) * SROW + (k0 + b_ke) * 2;
                u32 r[4];
                LDMX4(r, addr);
                bf[2 * nt2][0] = r[0]; bf[2 * nt2][1] = r[1];
                bf[2 * nt2 + 1][0] = r[2]; bf[2 * nt2 + 1][1] = r[3];
            }
#pragma unroll
            for (int mt = 0; mt < 2; mt++)
#pragma unroll
                for (int nt = 0; nt < 8; nt++)
                    MMA_F16(acc[mt][nt], af[mt], bf[nt]);
        }
        __syncthreads();
    }

    // ---------------- epilogue: stage fp32 tile in smem, coalesced out -----
    float* stage = (float*)smem;                    // [128][132]
    const int l4 = lane >> 2, l2 = (lane & 3) * 2;

#pragma unroll
    for (int mt = 0; mt < 2; mt++) {
        const int lr = wm * 32 + mt * 16 + l4;
        const int grow = mtile * 128 + lr;
        float br0 = 0.f, br1 = 0.f;
        if (bias_mode == 2) { br0 = bias[grow]; br1 = bias[grow + 8]; }
#pragma unroll
        for (int nt = 0; nt < 8; nt++) {
            const int lc = wn * 64 + nt * 8 + l2;
            float bc0 = 0.f, bc1 = 0.f;
            if (bias_mode == 1) {
                bc0 = bias[ntile * 128 + lc];
                bc1 = bias[ntile * 128 + lc + 1];
            }
            float v0 = (acc[mt][nt][0] + bc0 + br0) * alpha;
            float v1 = (acc[mt][nt][1] + bc1 + br0) * alpha;
            float v2 = (acc[mt][nt][2] + bc0 + br1) * alpha;
            float v3 = (acc[mt][nt][3] + bc1 + br1) * alpha;
            if (do_relu) {
                v0 = fmaxf(v0, 0.f); v1 = fmaxf(v1, 0.f);
                v2 = fmaxf(v2, 0.f); v3 = fmaxf(v3, 0.f);
            }
            stage[lr * 132 + lc] = v0;
            stage[lr * 132 + lc + 1] = v1;
            stage[(lr + 8) * 132 + lc] = v2;
            stage[(lr + 8) * 132 + lc + 1] = v3;
        }
    }
    __syncthreads();

    if (out_mode == 0) {
        float* Cp = Cf + (long long)z * strideZ
                  + (long long)(mtile * 128) * ldc + ntile * 128;
#pragma unroll
        for (int i = 0; i < 16; i++) {
            const int idx = tid + i * 256;           // 0..4095
            const int rr = idx >> 5, c4 = (idx & 31) * 4;
            float4 v = *(float4*)&stage[rr * 132 + c4];
            *(float4*)(Cp + (long long)rr * ldc + c4) = v;
        }
    } else {
        fp16* Hp = Ch + (long long)(mtile * 128) * ldc + ntile * 128;
#pragma unroll
        for (int i = 0; i < 16; i++) {
            const int idx = tid + i * 256;
            const int rr = idx >> 5, c4 = (idx & 31) * 4;
            float4 v = *(float4*)&stage[rr * 132 + c4];
            __half2 h0 = __floats2half2_rn(v.x, v.y);
            __half2 h1 = __floats2half2_rn(v.z, v.w);
            __half2* hq = (__half2*)(Hp + (long long)rr * ldc + c4);
            hq[0] = h0; hq[1] = h1;
        }
    }
}

// ======================= elementwise kernels ===============================
__global__ void cvt4(const float4* __restrict__ x, __half2* __restrict__ h, int n4)
{
    int i = blockIdx.x * 256 + threadIdx.x;
    if (i >= n4) return;
    float4 v = x[i];
    h[2 * i]     = __floats2half2_rn(v.x, v.y);
    h[2 * i + 1] = __floats2half2_rn(v.z, v.w);
}

__global__ void prep_kernel(const float* __restrict__ q, const float* __restrict__ prev,
                            fp16* __restrict__ qbh, fp16* __restrict__ cath)
{
    int i = blockIdx.x * 256 + threadIdx.x;     // SEQ*BATCH*DIM
    int d = i & (DIM - 1);
    int t = i >> 9;
    int b = t & (BATCH - 1);
    int s = t >> 2;
    int r = b * SEQ + s;
    qbh[(size_t)r * DIM + d] = __float2half(q[i]);
    cath[(size_t)r * 2 * DIM + DIM + d] = __float2half(prev[i]);
}

__device__ __forceinline__ float fast_exp(float x) {
    float t = x * 1.4426950408889634f;
    t = fmaxf(t, -125.0f);
    float fi = floorf(t);
    float f = t - fi;
    float p = 1.5403530393381608e-4f;
    p = fmaf(p, f, 1.3333558146428443e-3f);
    p = fmaf(p, f, 9.618129107628477e-3f);
    p = fmaf(p, f, 5.550410866482158e-2f);
    p = fmaf(p, f, 2.402265069591007e-1f);
    p = fmaf(p, f, 6.931471805599453e-1f);
    p = fmaf(p, f, 1.0f);
    return p * __int_as_float(((int)fi + 127) << 23);
}

__global__ void softmax_rows(const float* __restrict__ logits,
                             __half2* __restrict__ wh, float* __restrict__ invsum)
{
    const int r = blockIdx.x;
    const float* row = logits + (size_t)r * NKV;
    const int tid = threadIdx.x;               // 256
    __shared__ float red[8];

    float m = -1e30f;
    for (int i = tid * 4; i < NKV; i += 1024) {
        float4 v = *(const float4*)(row + i);
        m = fmaxf(m, fmaxf(fmaxf(v.x, v.y), fmaxf(v.z, v.w)));
    }
#pragma unroll
    for (int o = 16; o; o >>= 1) m = fmaxf(m, __shfl_xor_sync(0xffffffffu, m, o));
    if ((tid & 31) == 0) red[tid >> 5] = m;
    __syncthreads();
    if (tid == 0) {
        float mm = red[0];
        for (int w = 1; w < 8; w++) mm = fmaxf(mm, red[w]);
        red[0] = mm;
    }
    __syncthreads();
    m = red[0];
    __syncthreads();

    float s = 0.f;
    for (int i = tid * 4; i < NKV; i += 1024) {
        float4 v = *(const float4*)(row + i);
        float e0 = fast_exp(v.x - m), e1 = fast_exp(v.y - m);
        float e2 = fast_exp(v.z - m), e3 = fast_exp(v.w - m);
        s += (e0 + e1) + (e2 + e3);
        size_t o2 = ((size_t)r * NKV + i) >> 1;
        wh[o2]     = __floats2half2_rn(e0, e1);
        wh[o2 + 1] = __floats2half2_rn(e2, e3);
    }
#pragma unroll
    for (int o = 16; o; o >>= 1) s += __shfl_xor_sync(0xffffffffu, s, o);
    if ((tid & 31) == 0) red[tid >> 5] = s;
    __syncthreads();
    if (tid == 0) {
        float ss = 0.f;
        for (int w = 0; w < 8; w++) ss += red[w];
        invsum[r] = 1.0f / ss;
    }
}

__global__ void attn_reduce(const float* __restrict__ part, const float* __restrict__ invsum,
                            float* __restrict__ attn, fp16* __restrict__ cath)
{
    int i = blockIdx.x * 256 + threadIdx.x;     // RQ*DIM
    int r = i >> 9;
    int d = i & (DIM - 1);
    float s = 0.f;
#pragma unroll
    for (int z = 0; z < ASPLIT; z++) s += part[(size_t)z * RQ * DIM + i];
    float v = s * invsum[r];
    attn[i] = v;
    cath[(size_t)r * 2 * DIM + d] = __float2half(v);
}

__global__ void sigma_kernel(const float* __restrict__ h, const float* __restrict__ Wg2,
                             const float* __restrict__ bg2, float* __restrict__ sig)
{
    const int r = blockIdx.x;
    const int tid = threadIdx.x;               // 128
    float s = 0.f;
    for (int i = tid; i < DIM; i += 128)
        s = fmaf(h[(size_t)r * DIM + i], Wg2[i], s);
#pragma unroll
    for (int o = 16; o; o >>= 1) s += __shfl_xor_sync(0xffffffffu, s, o);
    __shared__ float red[4];
    if ((tid & 31) == 0) red[tid >> 5] = s;
    __syncthreads();
    if (tid == 0) {
        float t = red[0] + red[1] + red[2] + red[3] + bg2[0];
        sig[r] = 1.0f / (1.0f + __expf(-t));
    }
}

__global__ void final_kernel(const float* __restrict__ attn, const float* __restrict__ prev,
                             const float* __restrict__ sig, float* __restrict__ out)
{
    int i = blockIdx.x * 256 + threadIdx.x;     // SEQ*BATCH*DIM
    int d = i & (DIM - 1);
    int t = i >> 9;
    int b = t & (BATCH - 1);
    int s = t >> 2;
    int r = b * SEQ + s;
    float g = sig[r];
    float a = attn[(size_t)r * DIM + d];
    float p = prev[i];
    out[i] = fmaf(a - p, g, p);
}

// ======================= launch =============================================
extern "C" void kernel_launch(void* const* d_in, const int* in_sizes, int n_in,
                              void* d_out, int out_size)
{
    (void)in_sizes; (void)n_in; (void)out_size;
    const float* q    = (const float*)d_in[0];
    const float* prev = (const float*)d_in[1];
    const float* Wq   = (const float*)d_in[2];
    const float* bq   = (const float*)d_in[3];
    const float* Wk   = (const float*)d_in[4];
    const float* bk   = (const float*)d_in[5];
    const float* Wv   = (const float*)d_in[6];
    const float* bv   = (const float*)d_in[7];
    const float* Wg1  = (const float*)d_in[8];
    const float* bg1  = (const float*)d_in[9];
    const float* Wg2  = (const float*)d_in[10];
    const float* bg2  = (const float*)d_in[11];
    const float* dk   = (const float*)d_in[12];
    const float* dv   = (const float*)d_in[13];
    float* out = (float*)d_out;

    cudaFuncSetAttribute(gemm_f16, cudaFuncAttributeMaxDynamicSharedMemorySize, GSMEM);

    fp16 *dkh, *dvh, *kh, *vth, *qbh, *qh, *wqh, *wkh, *wvh, *g1h, *wh, *cath;
    float *lg, *hbuf, *attn, *inv, *sg, *part;
    cudaGetSymbolAddress((void**)&dkh, g_dkh);
    cudaGetSymbolAddress((void**)&dvh, g_dvh);
    cudaGetSymbolAddress((void**)&kh,  g_kh);
    cudaGetSymbolAddress((void**)&vth, g_vth);
    cudaGetSymbolAddress((void**)&qbh, g_qbh);
    cudaGetSymbolAddress((void**)&qh,  g_qh);
    cudaGetSymbolAddress((void**)&wqh, g_wqh);
    cudaGetSymbolAddress((void**)&wkh, g_wkh);
    cudaGetSymbolAddress((void**)&wvh, g_wvh);
    cudaGetSymbolAddress((void**)&g1h, g_g1h);
    cudaGetSymbolAddress((void**)&wh,  g_wh);
    cudaGetSymbolAddress((void**)&cath, g_cath);
    cudaGetSymbolAddress((void**)&lg,  g_logits);
    cudaGetSymbolAddress((void**)&hbuf, g_hbuf);
    cudaGetSymbolAddress((void**)&attn, g_attn);
    cudaGetSymbolAddress((void**)&inv, g_invsum);
    cudaGetSymbolAddress((void**)&sg,  g_sigma);
    cudaGetSymbolAddress((void**)&part, g_part);

    const float q_alpha = 0.08838834764831845f;   // D^-0.5 / TEMP

    // --- input conversions to fp16 ---
    cvt4<<<(NKV * DIM / 4) / 256, 256>>>((const float4*)dk, (__half2*)dkh, NKV * DIM / 4);
    cvt4<<<(NKV * DIM / 4) / 256, 256>>>((const float4*)dv, (__half2*)dvh, NKV * DIM / 4);
    cvt4<<<(DIM * DIM / 4) / 256, 256>>>((const float4*)Wq, (__half2*)wqh, DIM * DIM / 4);
    cvt4<<<(DIM * DIM / 4) / 256, 256>>>((const float4*)Wk, (__half2*)wkh, DIM * DIM / 4);
    cvt4<<<(DIM * DIM / 4) / 256, 256>>>((const float4*)Wv, (__half2*)wvh, DIM * DIM / 4);
    cvt4<<<(DIM * 2 * DIM / 4) / 256, 256>>>((const float4*)Wg1, (__half2*)g1h, DIM * 2 * DIM / 4);
    prep_kernel<<<(SEQ * BATCH * DIM) / 256, 256>>>(q, prev, qbh, cath);

    // --- K projection: [NKV,DIM] = dk @ Wk^T + bk -> fp16 ---
    gemm_f16<<<dim3(DIM / 128, NKV / 128, 1), 256, GSMEM>>>(
        dkh, wkh, nullptr, kh,
        DIM, DIM, DIM, DIM, bk, 1, 1.f, 0, 0, 1, 0);

    // --- V^T projection: [DIM,NKV] = Wv @ dv^T (+bv per row) -> fp16 ---
    gemm_f16<<<dim3(NKV / 128, DIM / 128, 1), 256, GSMEM>>>(
        wvh, dvh, nullptr, vth,
        DIM, DIM, NKV, DIM, bv, 2, 1.f, 0, 0, 1, 0);

    // --- Q projection: [RQ,DIM] = (qb @ Wq^T + bq) * alpha -> fp16 ---
    gemm_f16<<<dim3(DIM / 128, RQ / 128, 1), 256, GSMEM>>>(
        qbh, wqh, nullptr, qh,
        DIM, DIM, DIM, DIM, bq, 1, q_alpha, 0, 0, 1, 0);

    // --- logits: [RQ,NKV] = q @ k^T -> fp32 (x = mtile so K-tiles shared) ---
    gemm_f16<<<dim3(RQ / 128, NKV / 128, 1), 256, GSMEM>>>(
        qh, kh, lg, nullptr,
        DIM, DIM, NKV, DIM, nullptr, 0, 1.f, 0, 1, 0, 0);

    // --- softmax -> unnormalized exp fp16 + invsum ---
    softmax_rows<<<RQ, 256>>>(lg, (__half2*)wh, inv);

    // --- attn split-K: part[z] = w @ vT over K-slices -> fp32 partials ---
    gemm_f16<<<dim3(DIM / 128, RQ / 128, ASPLIT), 256, GSMEM>>>(
        wh, vth, part, nullptr,
        NKV, NKV, DIM, AKSLICE, nullptr, 0, 1.f, 0, 0, 0, (long long)RQ * DIM);

    attn_reduce<<<(RQ * DIM) / 256, 256>>>(part, inv, attn, cath);

    // --- gate: h = relu(cat @ Wg1^T + bg1) -> fp32 ---
    gemm_f16<<<dim3(DIM / 128, RQ / 128, 1), 256, GSMEM>>>(
        cath, g1h, hbuf, nullptr,
        2 * DIM, 2 * DIM, DIM, 2 * DIM, bg1, 1, 1.f, 1, 0, 0, 0);

    sigma_kernel<<<RQ, 128>>>(hbuf, Wg2, bg2, sg);
    final_kernel<<<(SEQ * BATCH * DIM) / 256, 256>>>(attn, prev, sg, out);
}

// round 5
// speedup vs baseline: 6.2797x; 1.3648x over previous
#include <cuda_runtime.h>
#include <cuda_fp16.h>
#include <cuda_bf16.h>
#include <cstdint>

#define SEQ   256
#define BATCH 4
#define DIM   512
#define NKV   32768
#define RQ    (SEQ * BATCH)          // 1024
#define ASPLIT 8
#define AKSLICE (NKV / ASPLIT)       // 4096
#define NSUM  (NKV / 128)            // 256 logits n-tiles

typedef unsigned int u32;
typedef __half fp16;
typedef __nv_bfloat16 bf16;

// ======================= device scratch ====================================
__device__ __align__(16) fp16 g_dkh[NKV * DIM];
__device__ __align__(16) fp16 g_dvh[NKV * DIM];
__device__ __align__(16) fp16 g_kh [NKV * DIM];
__device__ __align__(16) bf16 g_vtb[NKV * DIM];      // V^T [DIM,NKV] bf16
__device__ __align__(16) fp16 g_qbh[RQ * DIM];
__device__ __align__(16) fp16 g_qh [RQ * DIM];
__device__ __align__(16) fp16 g_wqh[DIM * DIM];
__device__ __align__(16) fp16 g_wkh[DIM * DIM];
__device__ __align__(16) fp16 g_wvh[DIM * DIM];
__device__ __align__(16) fp16 g_g1h[DIM * 2 * DIM];
__device__ __align__(16) bf16 g_wb[(size_t)RQ * NKV];          // exp weights bf16, 64 MB
__device__ __align__(16) float g_sumpart[(size_t)RQ * NSUM];   // row partial sums
__device__ __align__(16) fp16 g_cath[RQ * 2 * DIM];
__device__ __align__(16) float g_hbuf[RQ * DIM];
__device__ __align__(16) float g_attn[RQ * DIM];
__device__ float g_invsum[RQ];
__device__ float g_sigma[RQ];
__device__ __align__(16) float g_part[(size_t)ASPLIT * RQ * DIM];

// ======================= PTX helpers =======================================
__device__ __forceinline__ u32 smem_u32(const void* p) {
    u32 a;
    asm("{ .reg .u64 t; cvta.to.shared.u64 t, %1; cvt.u32.u64 %0, t; }"
        : "=r"(a) : "l"(p));
    return a;
}

#define CP_ASYNC16(dst, src) \
    asm volatile("cp.async.cg.shared.global [%0], [%1], 16;" :: "r"(dst), "l"(src))
#define CP_COMMIT() asm volatile("cp.async.commit_group;" ::: "memory")
#define CP_WAIT(n)  asm volatile("cp.async.wait_group %0;" :: "n"(n) : "memory")

#define LDMX4(r, addr) \
    asm volatile("ldmatrix.sync.aligned.m8n8.x4.shared.b16 {%0,%1,%2,%3}, [%4];" \
        : "=r"((r)[0]), "=r"((r)[1]), "=r"((r)[2]), "=r"((r)[3]) : "r"(addr))

__device__ __forceinline__ void mma_tc(float* d, const u32* a, const u32* b, fp16) {
    asm volatile("mma.sync.aligned.m16n8k16.row.col.f32.f16.f16.f32 "
        "{%0,%1,%2,%3}, {%4,%5,%6,%7}, {%8,%9}, {%0,%1,%2,%3};"
        : "+f"(d[0]), "+f"(d[1]), "+f"(d[2]), "+f"(d[3])
        : "r"(a[0]), "r"(a[1]), "r"(a[2]), "r"(a[3]), "r"(b[0]), "r"(b[1]));
}
__device__ __forceinline__ void mma_tc(float* d, const u32* a, const u32* b, bf16) {
    asm volatile("mma.sync.aligned.m16n8k16.row.col.f32.bf16.bf16.f32 "
        "{%0,%1,%2,%3}, {%4,%5,%6,%7}, {%8,%9}, {%0,%1,%2,%3};"
        : "+f"(d[0]), "+f"(d[1]), "+f"(d[2]), "+f"(d[3])
        : "r"(a[0]), "r"(a[1]), "r"(a[2]), "r"(a[3]), "r"(b[0]), "r"(b[1]));
}

__device__ __forceinline__ float fast_exp(float x) {
    float t = x * 1.4426950408889634f;
    t = fmaxf(t, -125.0f);
    float fi = floorf(t);
    float f = t - fi;
    float p = 1.5403530393381608e-4f;
    p = fmaf(p, f, 1.3333558146428443e-3f);
    p = fmaf(p, f, 9.618129107628477e-3f);
    p = fmaf(p, f, 5.550410866482158e-2f);
    p = fmaf(p, f, 2.402265069591007e-1f);
    p = fmaf(p, f, 6.931471805599453e-1f);
    p = fmaf(p, f, 1.0f);
    return p * __int_as_float(((int)fi + 127) << 23);
}

// ======================= pipelined HMMA GEMM ===============================
// C[M,N] = A[M,K] * B[N,K]^T, T in {fp16, bf16}, fp32 accumulate
// out_mode: 0 fp32 C (+ split-K z*strideZ); 1 fp16; 2 bf16;
//           3 exp(acc)->bf16 + per-(row,ntile) partial sums
// bias_mode: 0 none, 1 per-col bias[n], 2 per-row bias[m]
#define GKC 64
#define SROW 144                   // bytes per smem row (128 data + 16 pad)
#define TILE_B (128 * SROW)        // 18432
#define STG_B (2 * TILE_B)         // A + B
#define GSMEM (2 * STG_B)          // 73728 (2 stages)

template<typename T>
__global__ __launch_bounds__(256, 2)
void gemm_t(const T* __restrict__ A, const T* __restrict__ B,
            float* __restrict__ Cf, void* __restrict__ Co,
            int lda, int ldb, int ldc, int kslice,
            const float* __restrict__ bias, int bias_mode,
            float alpha, int do_relu, int swap, int out_mode,
            long long strideZ, float* __restrict__ sums)
{
    extern __shared__ char smem[];
    const u32 sb = smem_u32(smem);
    const int tid = threadIdx.x;
    const int lane = tid & 31, wid = tid >> 5;
    const int wm = wid >> 1, wn = wid & 1;          // 4x2 warp grid
    const int mtile = swap ? blockIdx.x : blockIdx.y;
    const int ntile = swap ? blockIdx.y : blockIdx.x;
    const int z = blockIdx.z;
    const long long kbase = (long long)z * kslice;
    const int NC = kslice / GKC;

    auto load_stage = [&](int c) {
        const u32 st = sb + (u32)(c & 1) * STG_B;
        const long long kb = kbase + (long long)c * GKC;
#pragma unroll
        for (int i = 0; i < 4; i++) {               // A tile: 128 rows x 128B
            const int idx = tid + i * 256;           // 0..1023
            const int row = idx >> 3, ch = idx & 7;
            const u32 so = (u32)(row * SROW + ch * 16);
            const long long aoff = (long long)(mtile * 128 + row) * lda + kb + ch * 8;
            CP_ASYNC16(st + so, (const char*)(A + aoff));
        }
#pragma unroll
        for (int i = 0; i < 4; i++) {               // B tile
            const int idx = tid + i * 256;
            const int row = idx >> 3, ch = idx & 7;
            const u32 so = (u32)(row * SROW + ch * 16);
            const long long boff = (long long)(ntile * 128 + row) * ldb + kb + ch * 8;
            CP_ASYNC16(st + TILE_B + so, (const char*)(B + boff));
        }
        CP_COMMIT();
    };

    float acc[2][8][4];
#pragma unroll
    for (int mt = 0; mt < 2; mt++)
#pragma unroll
        for (int nt = 0; nt < 8; nt++)
#pragma unroll
            for (int j = 0; j < 4; j++) acc[mt][nt][j] = 0.f;

    load_stage(0);

    // ldmatrix lane addressing (element units)
    const u32 a_row = (u32)(wm * 32 + (lane & 15));
    const u32 a_ke  = (u32)((lane >> 4) * 8);
    const u32 b_row = (u32)(wn * 64 + ((lane >> 4) << 3) + (lane & 7));
    const u32 b_ke  = (u32)(((lane >> 3) & 1) * 8);

    for (int c = 0; c < NC; c++) {
        if (c + 1 < NC) { load_stage(c + 1); CP_WAIT(1); }
        else            { CP_WAIT(0); }
        __syncthreads();

        const u32 st = sb + (u32)(c & 1) * STG_B;
#pragma unroll
        for (int ks = 0; ks < 4; ks++) {
            const u32 k0 = ks * 16;
            u32 af[2][4], bfr[8][2];
#pragma unroll
            for (int mt = 0; mt < 2; mt++) {
                const u32 addr = st + (a_row + mt * 16) * SROW + (k0 + a_ke) * 2;
                LDMX4(af[mt], addr);
            }
#pragma unroll
            for (int nt2 = 0; nt2 < 4; nt2++) {
                const u32 addr = st + TILE_B + (b_row + nt2 * 16) * SROW + (k0 + b_ke) * 2;
                u32 r[4];
                LDMX4(r, addr);
                bfr[2 * nt2][0] = r[0]; bfr[2 * nt2][1] = r[1];
                bfr[2 * nt2 + 1][0] = r[2]; bfr[2 * nt2 + 1][1] = r[3];
            }
#pragma unroll
            for (int mt = 0; mt < 2; mt++)
#pragma unroll
                for (int nt = 0; nt < 8; nt++)
                    mma_tc(acc[mt][nt], af[mt], bfr[nt], T{});
        }
        __syncthreads();
    }

    // ---------------- epilogue: stage fp32 tile in smem, coalesced out -----
    float* stage = (float*)smem;                    // [128][132]
    const int l4 = lane >> 2, l2 = (lane & 3) * 2;

#pragma unroll
    for (int mt = 0; mt < 2; mt++) {
        const int lr = wm * 32 + mt * 16 + l4;
        const int grow = mtile * 128 + lr;
        float br0 = 0.f, br1 = 0.f;
        if (bias_mode == 2) { br0 = bias[grow]; br1 = bias[grow + 8]; }
#pragma unroll
        for (int nt = 0; nt < 8; nt++) {
            const int lc = wn * 64 + nt * 8 + l2;
            float v0, v1, v2, v3;
            if (out_mode == 3) {
                v0 = fast_exp(acc[mt][nt][0]);
                v1 = fast_exp(acc[mt][nt][1]);
                v2 = fast_exp(acc[mt][nt][2]);
                v3 = fast_exp(acc[mt][nt][3]);
            } else {
                float bc0 = 0.f, bc1 = 0.f;
                if (bias_mode == 1) {
                    bc0 = bias[ntile * 128 + lc];
                    bc1 = bias[ntile * 128 + lc + 1];
                }
                v0 = (acc[mt][nt][0] + bc0 + br0) * alpha;
                v1 = (acc[mt][nt][1] + bc1 + br0) * alpha;
                v2 = (acc[mt][nt][2] + bc0 + br1) * alpha;
                v3 = (acc[mt][nt][3] + bc1 + br1) * alpha;
                if (do_relu) {
                    v0 = fmaxf(v0, 0.f); v1 = fmaxf(v1, 0.f);
                    v2 = fmaxf(v2, 0.f); v3 = fmaxf(v3, 0.f);
                }
            }
            stage[lr * 132 + lc] = v0;
            stage[lr * 132 + lc + 1] = v1;
            stage[(lr + 8) * 132 + lc] = v2;
            stage[(lr + 8) * 132 + lc + 1] = v3;
        }
    }
    __syncthreads();

    if (out_mode == 0) {
        float* Cp = Cf + (long long)z * strideZ
                  + (long long)(mtile * 128) * ldc + ntile * 128;
#pragma unroll
        for (int i = 0; i < 16; i++) {
            const int idx = tid + i * 256;           // 0..4095
            const int rr = idx >> 5, c4 = (idx & 31) * 4;
            float4 v = *(float4*)&stage[rr * 132 + c4];
            *(float4*)(Cp + (long long)rr * ldc + c4) = v;
        }
    } else if (out_mode == 1) {
        fp16* Hp = (fp16*)Co + (long long)(mtile * 128) * ldc + ntile * 128;
#pragma unroll
        for (int i = 0; i < 16; i++) {
            const int idx = tid + i * 256;
            const int rr = idx >> 5, c4 = (idx & 31) * 4;
            float4 v = *(float4*)&stage[rr * 132 + c4];
            __half2* hq = (__half2*)(Hp + (long long)rr * ldc + c4);
            hq[0] = __floats2half2_rn(v.x, v.y);
            hq[1] = __floats2half2_rn(v.z, v.w);
        }
    } else {
        bf16* Bp = (bf16*)Co + (long long)(mtile * 128) * ldc + ntile * 128;
#pragma unroll
        for (int i = 0; i < 16; i++) {
            const int idx = tid + i * 256;
            const int rr = idx >> 5, c4 = (idx & 31) * 4;
            float4 v = *(float4*)&stage[rr * 132 + c4];
            __nv_bfloat162* bq = (__nv_bfloat162*)(Bp + (long long)rr * ldc + c4);
            bq[0] = __floats2bfloat162_rn(v.x, v.y);
            bq[1] = __floats2bfloat162_rn(v.z, v.w);
        }
        if (out_mode == 3) {
            // per-row partial sums: threads 2r, 2r+1 each sum one half-row
            const int r = tid >> 1, h = tid & 1;
            float s = 0.f;
            const float* rp = &stage[r * 132 + h * 64];
#pragma unroll
            for (int j = 0; j < 64; j++) s += rp[j];
            s += __shfl_xor_sync(0xffffffffu, s, 1);
            if (h == 0)
                sums[(size_t)(mtile * 128 + r) * NSUM + ntile] = s;
        }
    }
}

// ======================= elementwise kernels ===============================
__global__ void cvt4(const float4* __restrict__ x, __half2* __restrict__ h, int n4)
{
    int i = blockIdx.x * 256 + threadIdx.x;
    if (i >= n4) return;
    float4 v = x[i];
    h[2 * i]     = __floats2half2_rn(v.x, v.y);
    h[2 * i + 1] = __floats2half2_rn(v.z, v.w);
}

__global__ void prep_kernel(const float* __restrict__ q, const float* __restrict__ prev,
                            fp16* __restrict__ qbh, fp16* __restrict__ cath)
{
    int i = blockIdx.x * 256 + threadIdx.x;     // SEQ*BATCH*DIM
    int d = i & (DIM - 1);
    int t = i >> 9;
    int b = t & (BATCH - 1);
    int s = t >> 2;
    int r = b * SEQ + s;
    qbh[(size_t)r * DIM + d] = __float2half(q[i]);
    cath[(size_t)r * 2 * DIM + DIM + d] = __float2half(prev[i]);
}

__global__ void reduce_inv(const float* __restrict__ sp, float* __restrict__ inv)
{
    const int r = blockIdx.x;
    const int t = threadIdx.x;                  // 256
    __shared__ float red[8];
    float s = sp[(size_t)r * NSUM + t];
#pragma unroll
    for (int o = 16; o; o >>= 1) s += __shfl_xor_sync(0xffffffffu, s, o);
    if ((t & 31) == 0) red[t >> 5] = s;
    __syncthreads();
    if (t == 0) {
        float ss = 0.f;
        for (int w = 0; w < 8; w++) ss += red[w];
        inv[r] = 1.0f / ss;
    }
}

__global__ void attn_reduce(const float* __restrict__ part, const float* __restrict__ invsum,
                            float* __restrict__ attn, fp16* __restrict__ cath)
{
    int i = blockIdx.x * 256 + threadIdx.x;     // RQ*DIM
    int r = i >> 9;
    int d = i & (DIM - 1);
    float s = 0.f;
#pragma unroll
    for (int z = 0; z < ASPLIT; z++) s += part[(size_t)z * RQ * DIM + i];
    float v = s * invsum[r];
    attn[i] = v;
    cath[(size_t)r * 2 * DIM + d] = __float2half(v);
}

__global__ void sigma_kernel(const float* __restrict__ h, const float* __restrict__ Wg2,
                             const float* __restrict__ bg2, float* __restrict__ sig)
{
    const int r = blockIdx.x;
    const int tid = threadIdx.x;               // 128
    float s = 0.f;
    for (int i = tid; i < DIM; i += 128)
        s = fmaf(h[(size_t)r * DIM + i], Wg2[i], s);
#pragma unroll
    for (int o = 16; o; o >>= 1) s += __shfl_xor_sync(0xffffffffu, s, o);
    __shared__ float red[4];
    if ((tid & 31) == 0) red[tid >> 5] = s;
    __syncthreads();
    if (tid == 0) {
        float t = red[0] + red[1] + red[2] + red[3] + bg2[0];
        sig[r] = 1.0f / (1.0f + __expf(-t));
    }
}

__global__ void final_kernel(const float* __restrict__ attn, const float* __restrict__ prev,
                             const float* __restrict__ sig, float* __restrict__ out)
{
    int i = blockIdx.x * 256 + threadIdx.x;     // SEQ*BATCH*DIM
    int d = i & (DIM - 1);
    int t = i >> 9;
    int b = t & (BATCH - 1);
    int s = t >> 2;
    int r = b * SEQ + s;
    float g = sig[r];
    float a = attn[(size_t)r * DIM + d];
    float p = prev[i];
    out[i] = fmaf(a - p, g, p);
}

// ======================= launch =============================================
extern "C" void kernel_launch(void* const* d_in, const int* in_sizes, int n_in,
                              void* d_out, int out_size)
{
    (void)in_sizes; (void)n_in; (void)out_size;
    const float* q    = (const float*)d_in[0];
    const float* prev = (const float*)d_in[1];
    const float* Wq   = (const float*)d_in[2];
    const float* bq   = (const float*)d_in[3];
    const float* Wk   = (const float*)d_in[4];
    const float* bk   = (const float*)d_in[5];
    const float* Wv   = (const float*)d_in[6];
    const float* bv   = (const float*)d_in[7];
    const float* Wg1  = (const float*)d_in[8];
    const float* bg1  = (const float*)d_in[9];
    const float* Wg2  = (const float*)d_in[10];
    const float* bg2  = (const float*)d_in[11];
    const float* dk   = (const float*)d_in[12];
    const float* dv   = (const float*)d_in[13];
    float* out = (float*)d_out;

    cudaFuncSetAttribute(gemm_t<fp16>, cudaFuncAttributeMaxDynamicSharedMemorySize, GSMEM);
    cudaFuncSetAttribute(gemm_t<bf16>, cudaFuncAttributeMaxDynamicSharedMemorySize, GSMEM);

    fp16 *dkh, *dvh, *kh, *qbh, *qh, *wqh, *wkh, *wvh, *g1h, *cath;
    bf16 *vtb, *wb;
    float *hbuf, *attn, *inv, *sg, *part, *sp;
    cudaGetSymbolAddress((void**)&dkh, g_dkh);
    cudaGetSymbolAddress((void**)&dvh, g_dvh);
    cudaGetSymbolAddress((void**)&kh,  g_kh);
    cudaGetSymbolAddress((void**)&vtb, g_vtb);
    cudaGetSymbolAddress((void**)&qbh, g_qbh);
    cudaGetSymbolAddress((void**)&qh,  g_qh);
    cudaGetSymbolAddress((void**)&wqh, g_wqh);
    cudaGetSymbolAddress((void**)&wkh, g_wkh);
    cudaGetSymbolAddress((void**)&wvh, g_wvh);
    cudaGetSymbolAddress((void**)&g1h, g_g1h);
    cudaGetSymbolAddress((void**)&wb,  g_wb);
    cudaGetSymbolAddress((void**)&sp,  g_sumpart);
    cudaGetSymbolAddress((void**)&cath, g_cath);
    cudaGetSymbolAddress((void**)&hbuf, g_hbuf);
    cudaGetSymbolAddress((void**)&attn, g_attn);
    cudaGetSymbolAddress((void**)&inv, g_invsum);
    cudaGetSymbolAddress((void**)&sg,  g_sigma);
    cudaGetSymbolAddress((void**)&part, g_part);

    const float q_alpha = 0.08838834764831845f;   // D^-0.5 / TEMP

    // --- input conversions to fp16 ---
    cvt4<<<(NKV * DIM / 4) / 256, 256>>>((const float4*)dk, (__half2*)dkh, NKV * DIM / 4);
    cvt4<<<(NKV * DIM / 4) / 256, 256>>>((const float4*)dv, (__half2*)dvh, NKV * DIM / 4);
    cvt4<<<(DIM * DIM / 4) / 256, 256>>>((const float4*)Wq, (__half2*)wqh, DIM * DIM / 4);
    cvt4<<<(DIM * DIM / 4) / 256, 256>>>((const float4*)Wk, (__half2*)wkh, DIM * DIM / 4);
    cvt4<<<(DIM * DIM / 4) / 256, 256>>>((const float4*)Wv, (__half2*)wvh, DIM * DIM / 4);
    cvt4<<<(DIM * 2 * DIM / 4) / 256, 256>>>((const float4*)Wg1, (__half2*)g1h, DIM * 2 * DIM / 4);
    prep_kernel<<<(SEQ * BATCH * DIM) / 256, 256>>>(q, prev, qbh, cath);

    // --- K projection: [NKV,DIM] = dk @ Wk^T + bk -> fp16 ---
    gemm_t<fp16><<<dim3(DIM / 128, NKV / 128, 1), 256, GSMEM>>>(
        dkh, wkh, nullptr, kh,
        DIM, DIM, DIM, DIM, bk, 1, 1.f, 0, 0, 1, 0, nullptr);

    // --- V^T projection: [DIM,NKV] = Wv @ dv^T (+bv per row) -> bf16 ---
    gemm_t<fp16><<<dim3(NKV / 128, DIM / 128, 1), 256, GSMEM>>>(
        wvh, dvh, nullptr, vtb,
        DIM, DIM, NKV, DIM, bv, 2, 1.f, 0, 0, 2, 0, nullptr);

    // --- Q projection: [RQ,DIM] = (qb @ Wq^T + bq) * alpha -> fp16 ---
    gemm_t<fp16><<<dim3(DIM / 128, RQ / 128, 1), 256, GSMEM>>>(
        qbh, wqh, nullptr, qh,
        DIM, DIM, DIM, DIM, bq, 1, q_alpha, 0, 0, 1, 0, nullptr);

    // --- logits+exp fused: wb = exp(q @ k^T) bf16, + row partial sums ---
    gemm_t<fp16><<<dim3(RQ / 128, NKV / 128, 1), 256, GSMEM>>>(
        qh, kh, nullptr, wb,
        DIM, DIM, NKV, DIM, nullptr, 0, 1.f, 0, 1, 3, 0, sp);

    reduce_inv<<<RQ, NSUM>>>(sp, inv);

    // --- attn split-K: part[z] = w @ vT over K-slices -> fp32 partials ---
    gemm_t<bf16><<<dim3(DIM / 128, RQ / 128, ASPLIT), 256, GSMEM>>>(
        wb, vtb, part, nullptr,
        NKV, NKV, DIM, AKSLICE, nullptr, 0, 1.f, 0, 0, 0, (long long)RQ * DIM, nullptr);

    attn_reduce<<<(RQ * DIM) / 256, 256>>>(part, inv, attn, cath);

    // --- gate: h = relu(cat @ Wg1^T + bg1) -> fp32 ---
    gemm_t<fp16><<<dim3(DIM / 128, RQ / 128, 1), 256, GSMEM>>>(
        cath, g1h, hbuf, nullptr,
        2 * DIM, 2 * DIM, DIM, 2 * DIM, bg1, 1, 1.f, 1, 0, 0, 0, nullptr);

    sigma_kernel<<<RQ, 128>>>(hbuf, Wg2, bg2, sg);
    final_kernel<<<(SEQ * BATCH * DIM) / 256, 256>>>(attn, prev, sg, out);
}

// round 6
// speedup vs baseline: 6.3153x; 1.0057x over previous
#include <cuda_runtime.h>
#include <cuda_fp16.h>
#include <cuda_bf16.h>
#include <cstdint>

#define SEQ   256
#define BATCH 4
#define DIM   512
#define NKV   32768
#define RQ    (SEQ * BATCH)          // 1024
#define ASPLIT 8
#define AKSLICE (NKV / ASPLIT)       // 4096
#define NSUM  (NKV / 128)            // 256 logits n-tiles

typedef unsigned int u32;
typedef __half fp16;
typedef __nv_bfloat16 bf16;

// ======================= device scratch ====================================
__device__ __align__(16) fp16 g_dkh[NKV * DIM];
__device__ __align__(16) fp16 g_dvh[NKV * DIM];
__device__ __align__(16) fp16 g_kh [NKV * DIM];
__device__ __align__(16) bf16 g_vtb[NKV * DIM];      // V^T [DIM,NKV] bf16
__device__ __align__(16) fp16 g_qbh[RQ * DIM];
__device__ __align__(16) fp16 g_qh [RQ * DIM];
__device__ __align__(16) fp16 g_wqh[DIM * DIM];
__device__ __align__(16) fp16 g_wkh[DIM * DIM];
__device__ __align__(16) fp16 g_wvh[DIM * DIM];
__device__ __align__(16) fp16 g_g1h[DIM * 2 * DIM];
__device__ __align__(16) bf16 g_wb[(size_t)RQ * NKV];          // exp weights bf16
__device__ __align__(16) float g_sumpart[(size_t)RQ * NSUM];   // row partial sums
__device__ __align__(16) fp16 g_cath[RQ * 2 * DIM];
__device__ __align__(16) float g_hbuf[RQ * DIM];
__device__ __align__(16) float g_attn[RQ * DIM];
__device__ float g_invsum[RQ];
__device__ float g_sigma[RQ];
__device__ __align__(16) float g_part[(size_t)ASPLIT * RQ * DIM];

// ======================= PTX helpers =======================================
__device__ __forceinline__ u32 smem_u32(const void* p) {
    u32 a;
    asm("{ .reg .u64 t; cvta.to.shared.u64 t, %1; cvt.u32.u64 %0, t; }"
        : "=r"(a) : "l"(p));
    return a;
}

#define CP_ASYNC16(dst, src) \
    asm volatile("cp.async.cg.shared.global [%0], [%1], 16;" :: "r"(dst), "l"(src))
#define CP_COMMIT() asm volatile("cp.async.commit_group;" ::: "memory")
#define CP_WAIT(n)  asm volatile("cp.async.wait_group %0;" :: "n"(n) : "memory")

#define LDMX4(r, addr) \
    asm volatile("ldmatrix.sync.aligned.m8n8.x4.shared.b16 {%0,%1,%2,%3}, [%4];" \
        : "=r"((r)[0]), "=r"((r)[1]), "=r"((r)[2]), "=r"((r)[3]) : "r"(addr))

__device__ __forceinline__ void mma_tc(float* d, const u32* a, const u32* b, fp16) {
    asm volatile("mma.sync.aligned.m16n8k16.row.col.f32.f16.f16.f32 "
        "{%0,%1,%2,%3}, {%4,%5,%6,%7}, {%8,%9}, {%0,%1,%2,%3};"
        : "+f"(d[0]), "+f"(d[1]), "+f"(d[2]), "+f"(d[3])
        : "r"(a[0]), "r"(a[1]), "r"(a[2]), "r"(a[3]), "r"(b[0]), "r"(b[1]));
}
__device__ __forceinline__ void mma_tc(float* d, const u32* a, const u32* b, bf16) {
    asm volatile("mma.sync.aligned.m16n8k16.row.col.f32.bf16.bf16.f32 "
        "{%0,%1,%2,%3}, {%4,%5,%6,%7}, {%8,%9}, {%0,%1,%2,%3};"
        : "+f"(d[0]), "+f"(d[1]), "+f"(d[2]), "+f"(d[3])
        : "r"(a[0]), "r"(a[1]), "r"(a[2]), "r"(a[3]), "r"(b[0]), "r"(b[1]));
}

__device__ __forceinline__ float fast_exp(float x) {
    float t = x * 1.4426950408889634f;
    t = fmaxf(t, -125.0f);
    float fi = floorf(t);
    float f = t - fi;
    float p = 1.5403530393381608e-4f;
    p = fmaf(p, f, 1.3333558146428443e-3f);
    p = fmaf(p, f, 9.618129107628477e-3f);
    p = fmaf(p, f, 5.550410866482158e-2f);
    p = fmaf(p, f, 2.402265069591007e-1f);
    p = fmaf(p, f, 6.931471805599453e-1f);
    p = fmaf(p, f, 1.0f);
    return p * __int_as_float(((int)fi + 127) << 23);
}

// ======================= pipelined HMMA GEMM ===============================
// C[M,N] = A[M,K] * B[N,K]^T, T in {fp16, bf16}, fp32 accumulate
// out_mode: 0 fp32 C (+ split-K z*strideZ); 1 fp16; 2 bf16;
//           3 exp(acc)->bf16 + per-(row,ntile) partial sums
// bias_mode: 0 none, 1 per-col bias[n], 2 per-row bias[m]
#define GKC 64
#define SROW 144                   // bytes per smem row (128 data + 16 pad)
#define TILE_B (128 * SROW)        // 18432
#define STG_B (2 * TILE_B)         // A + B = 36864
#define GSMEM (3 * STG_B)          // 110592 (3 stages)

template<typename T>
__global__ __launch_bounds__(256, 2)
void gemm_t(const T* __restrict__ A, const T* __restrict__ B,
            float* __restrict__ Cf, void* __restrict__ Co,
            int lda, int ldb, int ldc, int kslice,
            const float* __restrict__ bias, int bias_mode,
            float alpha, int do_relu, int swap, int out_mode,
            long long strideZ, float* __restrict__ sums)
{
    extern __shared__ char smem[];
    const u32 sb = smem_u32(smem);
    const int tid = threadIdx.x;
    const int lane = tid & 31, wid = tid >> 5;
    const int wm = wid >> 1, wn = wid & 1;          // 4x2 warp grid
    const int mtile = swap ? blockIdx.x : blockIdx.y;
    const int ntile = swap ? blockIdx.y : blockIdx.x;
    const int z = blockIdx.z;
    const long long kbase = (long long)z * kslice;
    const int NC = kslice / GKC;

    auto load_stage = [&](int c) {
        const u32 st = sb + (u32)(c % 3) * STG_B;
        const long long kb = kbase + (long long)c * GKC;
#pragma unroll
        for (int i = 0; i < 4; i++) {               // A tile: 128 rows x 128B
            const int idx = tid + i * 256;           // 0..1023
            const int row = idx >> 3, ch = idx & 7;
            const u32 so = (u32)(row * SROW + ch * 16);
            const long long aoff = (long long)(mtile * 128 + row) * lda + kb + ch * 8;
            CP_ASYNC16(st + so, (const char*)(A + aoff));
        }
#pragma unroll
        for (int i = 0; i < 4; i++) {               // B tile
            const int idx = tid + i * 256;
            const int row = idx >> 3, ch = idx & 7;
            const u32 so = (u32)(row * SROW + ch * 16);
            const long long boff = (long long)(ntile * 128 + row) * ldb + kb + ch * 8;
            CP_ASYNC16(st + TILE_B + so, (const char*)(B + boff));
        }
        CP_COMMIT();
    };

    float acc[2][8][4];
#pragma unroll
    for (int mt = 0; mt < 2; mt++)
#pragma unroll
        for (int nt = 0; nt < 8; nt++)
#pragma unroll
            for (int j = 0; j < 4; j++) acc[mt][nt][j] = 0.f;

    load_stage(0);
    load_stage(1);

    // ldmatrix lane addressing (element units)
    const u32 a_row = (u32)(wm * 32 + (lane & 15));
    const u32 a_ke  = (u32)((lane >> 4) * 8);
    const u32 b_row = (u32)(wn * 64 + ((lane >> 4) << 3) + (lane & 7));
    const u32 b_ke  = (u32)(((lane >> 3) & 1) * 8);

    for (int c = 0; c < NC; c++) {
        if (c + 1 < NC) { CP_WAIT(1); } else { CP_WAIT(0); }
        __syncthreads();
        if (c + 2 < NC) load_stage(c + 2);          // into (c+2)%3, readers on c%3

        const u32 st = sb + (u32)(c % 3) * STG_B;
#pragma unroll
        for (int ks = 0; ks < 4; ks++) {
            const u32 k0 = ks * 16;
            u32 af[2][4], bfr[8][2];
#pragma unroll
            for (int mt = 0; mt < 2; mt++) {
                const u32 addr = st + (a_row + mt * 16) * SROW + (k0 + a_ke) * 2;
                LDMX4(af[mt], addr);
            }
#pragma unroll
            for (int nt2 = 0; nt2 < 4; nt2++) {
                const u32 addr = st + TILE_B + (b_row + nt2 * 16) * SROW + (k0 + b_ke) * 2;
                u32 r[4];
                LDMX4(r, addr);
                bfr[2 * nt2][0] = r[0]; bfr[2 * nt2][1] = r[1];
                bfr[2 * nt2 + 1][0] = r[2]; bfr[2 * nt2 + 1][1] = r[3];
            }
#pragma unroll
            for (int mt = 0; mt < 2; mt++)
#pragma unroll
                for (int nt = 0; nt < 8; nt++)
                    mma_tc(acc[mt][nt], af[mt], bfr[nt], T{});
        }
        // no bottom sync: next iter's top sync provides the barrier
    }
    __syncthreads();

    // ---------------- epilogue: stage fp32 tile in smem, coalesced out -----
    float* stage = (float*)smem;                    // [128][132]
    const int l4 = lane >> 2, l2 = (lane & 3) * 2;

#pragma unroll
    for (int mt = 0; mt < 2; mt++) {
        const int lr = wm * 32 + mt * 16 + l4;
        const int grow = mtile * 128 + lr;
        float br0 = 0.f, br1 = 0.f;
        if (bias_mode == 2) { br0 = bias[grow]; br1 = bias[grow + 8]; }
#pragma unroll
        for (int nt = 0; nt < 8; nt++) {
            const int lc = wn * 64 + nt * 8 + l2;
            float v0, v1, v2, v3;
            if (out_mode == 3) {
                v0 = fast_exp(acc[mt][nt][0]);
                v1 = fast_exp(acc[mt][nt][1]);
                v2 = fast_exp(acc[mt][nt][2]);
                v3 = fast_exp(acc[mt][nt][3]);
            } else {
                float bc0 = 0.f, bc1 = 0.f;
                if (bias_mode == 1) {
                    bc0 = bias[ntile * 128 + lc];
                    bc1 = bias[ntile * 128 + lc + 1];
                }
                v0 = (acc[mt][nt][0] + bc0 + br0) * alpha;
                v1 = (acc[mt][nt][1] + bc1 + br0) * alpha;
                v2 = (acc[mt][nt][2] + bc0 + br1) * alpha;
                v3 = (acc[mt][nt][3] + bc1 + br1) * alpha;
                if (do_relu) {
                    v0 = fmaxf(v0, 0.f); v1 = fmaxf(v1, 0.f);
                    v2 = fmaxf(v2, 0.f); v3 = fmaxf(v3, 0.f);
                }
            }
            stage[lr * 132 + lc] = v0;
            stage[lr * 132 + lc + 1] = v1;
            stage[(lr + 8) * 132 + lc] = v2;
            stage[(lr + 8) * 132 + lc + 1] = v3;
        }
    }
    __syncthreads();

    if (out_mode == 0) {
        float* Cp = Cf + (long long)z * strideZ
                  + (long long)(mtile * 128) * ldc + ntile * 128;
#pragma unroll
        for (int i = 0; i < 16; i++) {
            const int idx = tid + i * 256;           // 0..4095
            const int rr = idx >> 5, c4 = (idx & 31) * 4;
            float4 v = *(float4*)&stage[rr * 132 + c4];
            *(float4*)(Cp + (long long)rr * ldc + c4) = v;
        }
    } else if (out_mode == 1) {
        fp16* Hp = (fp16*)Co + (long long)(mtile * 128) * ldc + ntile * 128;
#pragma unroll
        for (int i = 0; i < 16; i++) {
            const int idx = tid + i * 256;
            const int rr = idx >> 5, c4 = (idx & 31) * 4;
            float4 v = *(float4*)&stage[rr * 132 + c4];
            __half2* hq = (__half2*)(Hp + (long long)rr * ldc + c4);
            hq[0] = __floats2half2_rn(v.x, v.y);
            hq[1] = __floats2half2_rn(v.z, v.w);
        }
    } else {
        bf16* Bp = (bf16*)Co + (long long)(mtile * 128) * ldc + ntile * 128;
#pragma unroll
        for (int i = 0; i < 16; i++) {
            const int idx = tid + i * 256;
            const int rr = idx >> 5, c4 = (idx & 31) * 4;
            float4 v = *(float4*)&stage[rr * 132 + c4];
            __nv_bfloat162* bq = (__nv_bfloat162*)(Bp + (long long)rr * ldc + c4);
            bq[0] = __floats2bfloat162_rn(v.x, v.y);
            bq[1] = __floats2bfloat162_rn(v.z, v.w);
        }
        if (out_mode == 3) {
            // per-row partial sums: threads 2r, 2r+1 each sum one half-row
            const int r = tid >> 1, h = tid & 1;
            float s = 0.f;
            const float* rp = &stage[r * 132 + h * 64];
#pragma unroll
            for (int j = 0; j < 64; j++) s += rp[j];
            s += __shfl_xor_sync(0xffffffffu, s, 1);
            if (h == 0)
                sums[(size_t)(mtile * 128 + r) * NSUM + ntile] = s;
        }
    }
}

// ======================= elementwise kernels ===============================
__global__ void cvt4(const float4* __restrict__ x, __half2* __restrict__ h, int n4)
{
    int i = blockIdx.x * 256 + threadIdx.x;
    if (i >= n4) return;
    float4 v = x[i];
    h[2 * i]     = __floats2half2_rn(v.x, v.y);
    h[2 * i + 1] = __floats2half2_rn(v.z, v.w);
}

__global__ void prep_kernel(const float* __restrict__ q, const float* __restrict__ prev,
                            fp16* __restrict__ qbh, fp16* __restrict__ cath)
{
    int i = blockIdx.x * 256 + threadIdx.x;     // SEQ*BATCH*DIM
    int d = i & (DIM - 1);
    int t = i >> 9;
    int b = t & (BATCH - 1);
    int s = t >> 2;
    int r = b * SEQ + s;
    qbh[(size_t)r * DIM + d] = __float2half(q[i]);
    cath[(size_t)r * 2 * DIM + DIM + d] = __float2half(prev[i]);
}

__global__ void reduce_inv(const float* __restrict__ sp, float* __restrict__ inv)
{
    const int r = blockIdx.x;
    const int t = threadIdx.x;                  // 256
    __shared__ float red[8];
    float s = sp[(size_t)r * NSUM + t];
#pragma unroll
    for (int o = 16; o; o >>= 1) s += __shfl_xor_sync(0xffffffffu, s, o);
    if ((t & 31) == 0) red[t >> 5] = s;
    __syncthreads();
    if (t == 0) {
        float ss = 0.f;
        for (int w = 0; w < 8; w++) ss += red[w];
        inv[r] = 1.0f / ss;
    }
}

__global__ void attn_reduce(const float* __restrict__ part, const float* __restrict__ invsum,
                            float* __restrict__ attn, fp16* __restrict__ cath)
{
    int i = blockIdx.x * 256 + threadIdx.x;     // RQ*DIM
    int r = i >> 9;
    int d = i & (DIM - 1);
    float s = 0.f;
#pragma unroll
    for (int z = 0; z < ASPLIT; z++) s += part[(size_t)z * RQ * DIM + i];
    float v = s * invsum[r];
    attn[i] = v;
    cath[(size_t)r * 2 * DIM + d] = __float2half(v);
}

__global__ void sigma_kernel(const float* __restrict__ h, const float* __restrict__ Wg2,
                             const float* __restrict__ bg2, float* __restrict__ sig)
{
    const int r = blockIdx.x;
    const int tid = threadIdx.x;               // 128
    float s = 0.f;
    for (int i = tid; i < DIM; i += 128)
        s = fmaf(h[(size_t)r * DIM + i], Wg2[i], s);
#pragma unroll
    for (int o = 16; o; o >>= 1) s += __shfl_xor_sync(0xffffffffu, s, o);
    __shared__ float red[4];
    if ((tid & 31) == 0) red[tid >> 5] = s;
    __syncthreads();
    if (tid == 0) {
        float t = red[0] + red[1] + red[2] + red[3] + bg2[0];
        sig[r] = 1.0f / (1.0f + __expf(-t));
    }
}

__global__ void final_kernel(const float* __restrict__ attn, const float* __restrict__ prev,
                             const float* __restrict__ sig, float* __restrict__ out)
{
    int i = blockIdx.x * 256 + threadIdx.x;     // SEQ*BATCH*DIM
    int d = i & (DIM - 1);
    int t = i >> 9;
    int b = t & (BATCH - 1);
    int s = t >> 2;
    int r = b * SEQ + s;
    float g = sig[r];
    float a = attn[(size_t)r * DIM + d];
    float p = prev[i];
    out[i] = fmaf(a - p, g, p);
}

// ======================= launch =============================================
extern "C" void kernel_launch(void* const* d_in, const int* in_sizes, int n_in,
                              void* d_out, int out_size)
{
    (void)in_sizes; (void)n_in; (void)out_size;
    const float* q    = (const float*)d_in[0];
    const float* prev = (const float*)d_in[1];
    const float* Wq   = (const float*)d_in[2];
    const float* bq   = (const float*)d_in[3];
    const float* Wk   = (const float*)d_in[4];
    const float* bk   = (const float*)d_in[5];
    const float* Wv   = (const float*)d_in[6];
    const float* bv   = (const float*)d_in[7];
    const float* Wg1  = (const float*)d_in[8];
    const float* bg1  = (const float*)d_in[9];
    const float* Wg2  = (const float*)d_in[10];
    const float* bg2  = (const float*)d_in[11];
    const float* dk   = (const float*)d_in[12];
    const float* dv   = (const float*)d_in[13];
    float* out = (float*)d_out;

    cudaFuncSetAttribute(gemm_t<fp16>, cudaFuncAttributeMaxDynamicSharedMemorySize, GSMEM);
    cudaFuncSetAttribute(gemm_t<bf16>, cudaFuncAttributeMaxDynamicSharedMemorySize, GSMEM);

    fp16 *dkh, *dvh, *kh, *qbh, *qh, *wqh, *wkh, *wvh, *g1h, *cath;
    bf16 *vtb, *wb;
    float *hbuf, *attn, *inv, *sg, *part, *sp;
    cudaGetSymbolAddress((void**)&dkh, g_dkh);
    cudaGetSymbolAddress((void**)&dvh, g_dvh);
    cudaGetSymbolAddress((void**)&kh,  g_kh);
    cudaGetSymbolAddress((void**)&vtb, g_vtb);
    cudaGetSymbolAddress((void**)&qbh, g_qbh);
    cudaGetSymbolAddress((void**)&qh,  g_qh);
    cudaGetSymbolAddress((void**)&wqh, g_wqh);
    cudaGetSymbolAddress((void**)&wkh, g_wkh);
    cudaGetSymbolAddress((void**)&wvh, g_wvh);
    cudaGetSymbolAddress((void**)&g1h, g_g1h);
    cudaGetSymbolAddress((void**)&wb,  g_wb);
    cudaGetSymbolAddress((void**)&sp,  g_sumpart);
    cudaGetSymbolAddress((void**)&cath, g_cath);
    cudaGetSymbolAddress((void**)&hbuf, g_hbuf);
    cudaGetSymbolAddress((void**)&attn, g_attn);
    cudaGetSymbolAddress((void**)&inv, g_invsum);
    cudaGetSymbolAddress((void**)&sg,  g_sigma);
    cudaGetSymbolAddress((void**)&part, g_part);

    const float q_alpha = 0.08838834764831845f;   // D^-0.5 / TEMP

    // --- input conversions to fp16 ---
    cvt4<<<(NKV * DIM / 4) / 256, 256>>>((const float4*)dk, (__half2*)dkh, NKV * DIM / 4);
    cvt4<<<(NKV * DIM / 4) / 256, 256>>>((const float4*)dv, (__half2*)dvh, NKV * DIM / 4);
    cvt4<<<(DIM * DIM / 4) / 256, 256>>>((const float4*)Wq, (__half2*)wqh, DIM * DIM / 4);
    cvt4<<<(DIM * DIM / 4) / 256, 256>>>((const float4*)Wk, (__half2*)wkh, DIM * DIM / 4);
    cvt4<<<(DIM * DIM / 4) / 256, 256>>>((const float4*)Wv, (__half2*)wvh, DIM * DIM / 4);
    cvt4<<<(DIM * 2 * DIM / 4) / 256, 256>>>((const float4*)Wg1, (__half2*)g1h, DIM * 2 * DIM / 4);
    prep_kernel<<<(SEQ * BATCH * DIM) / 256, 256>>>(q, prev, qbh, cath);

    // --- K projection: [NKV,DIM] = dk @ Wk^T + bk -> fp16 ---
    gemm_t<fp16><<<dim3(DIM / 128, NKV / 128, 1), 256, GSMEM>>>(
        dkh, wkh, nullptr, kh,
        DIM, DIM, DIM, DIM, bk, 1, 1.f, 0, 0, 1, 0, nullptr);

    // --- V^T projection: [DIM,NKV] = Wv @ dv^T (+bv per row) -> bf16 ---
    // swap=1 so consecutive CTAs share the streamed dvh tile (B read once)
    gemm_t<fp16><<<dim3(DIM / 128, NKV / 128, 1), 256, GSMEM>>>(
        wvh, dvh, nullptr, vtb,
        DIM, DIM, NKV, DIM, bv, 2, 1.f, 0, 1, 2, 0, nullptr);

    // --- Q projection: [RQ,DIM] = (qb @ Wq^T + bq) * alpha -> fp16 ---
    gemm_t<fp16><<<dim3(DIM / 128, RQ / 128, 1), 256, GSMEM>>>(
        qbh, wqh, nullptr, qh,
        DIM, DIM, DIM, DIM, bq, 1, q_alpha, 0, 0, 1, 0, nullptr);

    // --- logits+exp fused: wb = exp(q @ k^T) bf16, + row partial sums ---
    gemm_t<fp16><<<dim3(RQ / 128, NKV / 128, 1), 256, GSMEM>>>(
        qh, kh, nullptr, wb,
        DIM, DIM, NKV, DIM, nullptr, 0, 1.f, 0, 1, 3, 0, sp);

    reduce_inv<<<RQ, NSUM>>>(sp, inv);

    // --- attn split-K: part[z] = w @ vT over K-slices -> fp32 partials ---
    gemm_t<bf16><<<dim3(DIM / 128, RQ / 128, ASPLIT), 256, GSMEM>>>(
        wb, vtb, part, nullptr,
        NKV, NKV, DIM, AKSLICE, nullptr, 0, 1.f, 0, 0, 0, (long long)RQ * DIM, nullptr);

    attn_reduce<<<(RQ * DIM) / 256, 256>>>(part, inv, attn, cath);

    // --- gate: h = relu(cat @ Wg1^T + bg1) -> fp32 ---
    gemm_t<fp16><<<dim3(DIM / 128, RQ / 128, 1), 256, GSMEM>>>(
        cath, g1h, hbuf, nullptr,
        2 * DIM, 2 * DIM, DIM, 2 * DIM, bg1, 1, 1.f, 1, 0, 0, 0, nullptr);

    sigma_kernel<<<RQ, 128>>>(hbuf, Wg2, bg2, sg);
    final_kernel<<<(SEQ * BATCH * DIM) / 256, 256>>>(attn, prev, sg, out);
}

// round 7
// speedup vs baseline: 7.9517x; 1.2591x over previous
#include <cuda_runtime.h>
#include <cuda_fp16.h>
#include <cuda_bf16.h>
#include <cstdint>

#define SEQ   256
#define BATCH 4
#define DIM   512
#define NKV   32768
#define RQ    (SEQ * BATCH)          // 1024
#define ASPLIT 8
#define AKSLICE (NKV / ASPLIT)       // 4096
#define NSUM  (NKV / 128)            // 256 logits n-tiles

typedef unsigned int u32;
typedef __half fp16;
typedef __nv_bfloat16 bf16;

// ======================= device scratch ====================================
__device__ __align__(16) fp16 g_dkh[NKV * DIM];            // dk fp16
__device__ __align__(16) bf16 g_dvt[NKV * DIM];            // dv^T [DIM,NKV] bf16
__device__ __align__(16) fp16 g_qbh[RQ * DIM];
__device__ __align__(16) fp16 g_qh [RQ * DIM];             // _q
__device__ __align__(16) fp16 g_q2 [RQ * DIM];             // _q @ Wk (scaled)
__device__ __align__(16) fp16 g_wqh[DIM * DIM];
__device__ __align__(16) fp16 g_wkt[DIM * DIM];            // Wk^T fp16
__device__ __align__(16) fp16 g_wvh[DIM * DIM];
__device__ __align__(16) fp16 g_g1h[DIM * 2 * DIM];
__device__ __align__(16) bf16 g_wb[(size_t)RQ * NKV];      // exp weights bf16
__device__ __align__(16) float g_sumpart[(size_t)RQ * NSUM];
__device__ __align__(16) fp16 g_attnp[RQ * DIM];           // w̄ @ dv, fp16
__device__ __align__(16) fp16 g_cath[RQ * 2 * DIM];
__device__ __align__(16) float g_hbuf[RQ * DIM];
__device__ __align__(16) float g_attn[RQ * DIM];
__device__ float g_invsum[RQ];
__device__ float g_sigma[RQ];
__device__ __align__(16) float g_part[(size_t)ASPLIT * RQ * DIM];

// ======================= PTX helpers =======================================
__device__ __forceinline__ u32 smem_u32(const void* p) {
    u32 a;
    asm("{ .reg .u64 t; cvta.to.shared.u64 t, %1; cvt.u32.u64 %0, t; }"
        : "=r"(a) : "l"(p));
    return a;
}

#define CP_ASYNC16(dst, src) \
    asm volatile("cp.async.cg.shared.global [%0], [%1], 16;" :: "r"(dst), "l"(src))
#define CP_COMMIT() asm volatile("cp.async.commit_group;" ::: "memory")
#define CP_WAIT(n)  asm volatile("cp.async.wait_group %0;" :: "n"(n) : "memory")

#define LDMX4(r, addr) \
    asm volatile("ldmatrix.sync.aligned.m8n8.x4.shared.b16 {%0,%1,%2,%3}, [%4];" \
        : "=r"((r)[0]), "=r"((r)[1]), "=r"((r)[2]), "=r"((r)[3]) : "r"(addr))

__device__ __forceinline__ void mma_tc(float* d, const u32* a, const u32* b, fp16) {
    asm volatile("mma.sync.aligned.m16n8k16.row.col.f32.f16.f16.f32 "
        "{%0,%1,%2,%3}, {%4,%5,%6,%7}, {%8,%9}, {%0,%1,%2,%3};"
        : "+f"(d[0]), "+f"(d[1]), "+f"(d[2]), "+f"(d[3])
        : "r"(a[0]), "r"(a[1]), "r"(a[2]), "r"(a[3]), "r"(b[0]), "r"(b[1]));
}
__device__ __forceinline__ void mma_tc(float* d, const u32* a, const u32* b, bf16) {
    asm volatile("mma.sync.aligned.m16n8k16.row.col.f32.bf16.bf16.f32 "
        "{%0,%1,%2,%3}, {%4,%5,%6,%7}, {%8,%9}, {%0,%1,%2,%3};"
        : "+f"(d[0]), "+f"(d[1]), "+f"(d[2]), "+f"(d[3])
        : "r"(a[0]), "r"(a[1]), "r"(a[2]), "r"(a[3]), "r"(b[0]), "r"(b[1]));
}

__device__ __forceinline__ float fast_exp(float x) {
    float t = x * 1.4426950408889634f;
    t = fmaxf(t, -125.0f);
    float fi = floorf(t);
    float f = t - fi;
    float p = 1.5403530393381608e-4f;
    p = fmaf(p, f, 1.3333558146428443e-3f);
    p = fmaf(p, f, 9.618129107628477e-3f);
    p = fmaf(p, f, 5.550410866482158e-2f);
    p = fmaf(p, f, 2.402265069591007e-1f);
    p = fmaf(p, f, 6.931471805599453e-1f);
    p = fmaf(p, f, 1.0f);
    return p * __int_as_float(((int)fi + 127) << 23);
}

// ======================= pipelined HMMA GEMM ===============================
// C[M,N] = A[M,K] * B[N,K]^T, T in {fp16, bf16}, fp32 accumulate
// out_mode: 0 fp32 (+ split-K z*strideZ); 1 fp16; 2 bf16;
//           3 exp(acc)->bf16 + per-(row,ntile) partial sums;
//           4 fp32 to Cf AND fp16 to Co (ld2 = strideZ)
// bias_mode: 0 none, 1 per-col bias[n], 2 per-row bias[m]
#define GKC 64
#define SROW 144
#define TILE_B (128 * SROW)
#define STG_B (2 * TILE_B)
#define GSMEM (3 * STG_B)

template<typename T>
__global__ __launch_bounds__(256, 2)
void gemm_t(const T* __restrict__ A, const T* __restrict__ B,
            float* __restrict__ Cf, void* __restrict__ Co,
            int lda, int ldb, int ldc, int kslice,
            const float* __restrict__ bias, int bias_mode,
            float alpha, int do_relu, int swap, int out_mode,
            long long strideZ, float* __restrict__ sums)
{
    extern __shared__ char smem[];
    const u32 sb = smem_u32(smem);
    const int tid = threadIdx.x;
    const int lane = tid & 31, wid = tid >> 5;
    const int wm = wid >> 1, wn = wid & 1;
    const int mtile = swap ? blockIdx.x : blockIdx.y;
    const int ntile = swap ? blockIdx.y : blockIdx.x;
    const int z = blockIdx.z;
    const long long kbase = (long long)z * kslice;
    const int NC = kslice / GKC;

    auto load_stage = [&](int c) {
        const u32 st = sb + (u32)(c % 3) * STG_B;
        const long long kb = kbase + (long long)c * GKC;
#pragma unroll
        for (int i = 0; i < 4; i++) {
            const int idx = tid + i * 256;
            const int row = idx >> 3, ch = idx & 7;
            const u32 so = (u32)(row * SROW + ch * 16);
            const long long aoff = (long long)(mtile * 128 + row) * lda + kb + ch * 8;
            CP_ASYNC16(st + so, (const char*)(A + aoff));
        }
#pragma unroll
        for (int i = 0; i < 4; i++) {
            const int idx = tid + i * 256;
            const int row = idx >> 3, ch = idx & 7;
            const u32 so = (u32)(row * SROW + ch * 16);
            const long long boff = (long long)(ntile * 128 + row) * ldb + kb + ch * 8;
            CP_ASYNC16(st + TILE_B + so, (const char*)(B + boff));
        }
        CP_COMMIT();
    };

    float acc[2][8][4];
#pragma unroll
    for (int mt = 0; mt < 2; mt++)
#pragma unroll
        for (int nt = 0; nt < 8; nt++)
#pragma unroll
            for (int j = 0; j < 4; j++) acc[mt][nt][j] = 0.f;

    load_stage(0);
    load_stage(1);

    const u32 a_row = (u32)(wm * 32 + (lane & 15));
    const u32 a_ke  = (u32)((lane >> 4) * 8);
    const u32 b_row = (u32)(wn * 64 + ((lane >> 4) << 3) + (lane & 7));
    const u32 b_ke  = (u32)(((lane >> 3) & 1) * 8);

    for (int c = 0; c < NC; c++) {
        if (c + 1 < NC) { CP_WAIT(1); } else { CP_WAIT(0); }
        __syncthreads();
        if (c + 2 < NC) load_stage(c + 2);

        const u32 st = sb + (u32)(c % 3) * STG_B;
#pragma unroll
        for (int ks = 0; ks < 4; ks++) {
            const u32 k0 = ks * 16;
            u32 af[2][4], bfr[8][2];
#pragma unroll
            for (int mt = 0; mt < 2; mt++) {
                const u32 addr = st + (a_row + mt * 16) * SROW + (k0 + a_ke) * 2;
                LDMX4(af[mt], addr);
            }
#pragma unroll
            for (int nt2 = 0; nt2 < 4; nt2++) {
                const u32 addr = st + TILE_B + (b_row + nt2 * 16) * SROW + (k0 + b_ke) * 2;
                u32 r[4];
                LDMX4(r, addr);
                bfr[2 * nt2][0] = r[0]; bfr[2 * nt2][1] = r[1];
                bfr[2 * nt2 + 1][0] = r[2]; bfr[2 * nt2 + 1][1] = r[3];
            }
#pragma unroll
            for (int mt = 0; mt < 2; mt++)
#pragma unroll
                for (int nt = 0; nt < 8; nt++)
                    mma_tc(acc[mt][nt], af[mt], bfr[nt], T{});
        }
    }
    __syncthreads();

    // ---------------- epilogue ---------------------------------------------
    float* stage = (float*)smem;                    // [128][132]
    const int l4 = lane >> 2, l2 = (lane & 3) * 2;

#pragma unroll
    for (int mt = 0; mt < 2; mt++) {
        const int lr = wm * 32 + mt * 16 + l4;
        const int grow = mtile * 128 + lr;
        float br0 = 0.f, br1 = 0.f;
        if (bias_mode == 2) { br0 = bias[grow]; br1 = bias[grow + 8]; }
#pragma unroll
        for (int nt = 0; nt < 8; nt++) {
            const int lc = wn * 64 + nt * 8 + l2;
            float v0, v1, v2, v3;
            if (out_mode == 3) {
                v0 = fast_exp(acc[mt][nt][0]);
                v1 = fast_exp(acc[mt][nt][1]);
                v2 = fast_exp(acc[mt][nt][2]);
                v3 = fast_exp(acc[mt][nt][3]);
            } else {
                float bc0 = 0.f, bc1 = 0.f;
                if (bias_mode == 1) {
                    bc0 = bias[ntile * 128 + lc];
                    bc1 = bias[ntile * 128 + lc + 1];
                }
                v0 = (acc[mt][nt][0] + bc0 + br0) * alpha;
                v1 = (acc[mt][nt][1] + bc1 + br0) * alpha;
                v2 = (acc[mt][nt][2] + bc0 + br1) * alpha;
                v3 = (acc[mt][nt][3] + bc1 + br1) * alpha;
                if (do_relu) {
                    v0 = fmaxf(v0, 0.f); v1 = fmaxf(v1, 0.f);
                    v2 = fmaxf(v2, 0.f); v3 = fmaxf(v3, 0.f);
                }
            }
            stage[lr * 132 + lc] = v0;
            stage[lr * 132 + lc + 1] = v1;
            stage[(lr + 8) * 132 + lc] = v2;
            stage[(lr + 8) * 132 + lc + 1] = v3;
        }
    }
    __syncthreads();

    if (out_mode == 0) {
        float* Cp = Cf + (long long)z * strideZ
                  + (long long)(mtile * 128) * ldc + ntile * 128;
#pragma unroll
        for (int i = 0; i < 16; i++) {
            const int idx = tid + i * 256;
            const int rr = idx >> 5, c4 = (idx & 31) * 4;
            float4 v = *(float4*)&stage[rr * 132 + c4];
            *(float4*)(Cp + (long long)rr * ldc + c4) = v;
        }
    } else if (out_mode == 1) {
        fp16* Hp = (fp16*)Co + (long long)(mtile * 128) * ldc + ntile * 128;
#pragma unroll
        for (int i = 0; i < 16; i++) {
            const int idx = tid + i * 256;
            const int rr = idx >> 5, c4 = (idx & 31) * 4;
            float4 v = *(float4*)&stage[rr * 132 + c4];
            __half2* hq = (__half2*)(Hp + (long long)rr * ldc + c4);
            hq[0] = __floats2half2_rn(v.x, v.y);
            hq[1] = __floats2half2_rn(v.z, v.w);
        }
    } else if (out_mode == 4) {
        const int ld2 = (int)strideZ;
        float* Cp = Cf + (long long)(mtile * 128) * ldc + ntile * 128;
        fp16* Hp = (fp16*)Co + (long long)(mtile * 128) * ld2 + ntile * 128;
#pragma unroll
        for (int i = 0; i < 16; i++) {
            const int idx = tid + i * 256;
            const int rr = idx >> 5, c4 = (idx & 31) * 4;
            float4 v = *(float4*)&stage[rr * 132 + c4];
            *(float4*)(Cp + (long long)rr * ldc + c4) = v;
            __half2* hq = (__half2*)(Hp + (long long)rr * ld2 + c4);
            hq[0] = __floats2half2_rn(v.x, v.y);
            hq[1] = __floats2half2_rn(v.z, v.w);
        }
    } else {
        bf16* Bp = (bf16*)Co + (long long)(mtile * 128) * ldc + ntile * 128;
#pragma unroll
        for (int i = 0; i < 16; i++) {
            const int idx = tid + i * 256;
            const int rr = idx >> 5, c4 = (idx & 31) * 4;
            float4 v = *(float4*)&stage[rr * 132 + c4];
            __nv_bfloat162* bq = (__nv_bfloat162*)(Bp + (long long)rr * ldc + c4);
            bq[0] = __floats2bfloat162_rn(v.x, v.y);
            bq[1] = __floats2bfloat162_rn(v.z, v.w);
        }
        if (out_mode == 3) {
            const int r = tid >> 1, h = tid & 1;
            float s = 0.f;
            const float* rp = &stage[r * 132 + h * 64];
#pragma unroll
            for (int j = 0; j < 64; j++) s += rp[j];
            s += __shfl_xor_sync(0xffffffffu, s, 1);
            if (h == 0)
                sums[(size_t)(mtile * 128 + r) * NSUM + ntile] = s;
        }
    }
}

// ======================= elementwise kernels ===============================
__global__ void cvt4(const float4* __restrict__ x, __half2* __restrict__ h, int n4)
{
    int i = blockIdx.x * 256 + threadIdx.x;
    if (i >= n4) return;
    float4 v = x[i];
    h[2 * i]     = __floats2half2_rn(v.x, v.y);
    h[2 * i + 1] = __floats2half2_rn(v.z, v.w);
}

// transpose + convert: src fp32 [R,C] -> dst T16 [C,R]
template<typename T>
__global__ void tcvt(const float* __restrict__ src, T* __restrict__ dst, int R, int C)
{
    __shared__ float tile[32][33];
    const int c0 = blockIdx.x * 32, r0 = blockIdx.y * 32;
    const int tx = threadIdx.x, ty = threadIdx.y;    // 32 x 8
#pragma unroll
    for (int i = 0; i < 32; i += 8)
        tile[ty + i][tx] = src[(size_t)(r0 + ty + i) * C + c0 + tx];
    __syncthreads();
#pragma unroll
    for (int i = 0; i < 32; i += 8)
        dst[(size_t)(c0 + ty + i) * R + r0 + tx] = (T)tile[tx][ty + i];
}

__global__ void prep_kernel(const float* __restrict__ q, const float* __restrict__ prev,
                            fp16* __restrict__ qbh, fp16* __restrict__ cath)
{
    int i = blockIdx.x * 256 + threadIdx.x;
    int d = i & (DIM - 1);
    int t = i >> 9;
    int b = t & (BATCH - 1);
    int s = t >> 2;
    int r = b * SEQ + s;
    qbh[(size_t)r * DIM + d] = __float2half(q[i]);
    cath[(size_t)r * 2 * DIM + DIM + d] = __float2half(prev[i]);
}

__global__ void reduce_inv(const float* __restrict__ sp, float* __restrict__ inv)
{
    const int r = blockIdx.x;
    const int t = threadIdx.x;
    __shared__ float red[8];
    float s = sp[(size_t)r * NSUM + t];
#pragma unroll
    for (int o = 16; o; o >>= 1) s += __shfl_xor_sync(0xffffffffu, s, o);
    if ((t & 31) == 0) red[t >> 5] = s;
    __syncthreads();
    if (t == 0) {
        float ss = 0.f;
        for (int w = 0; w < 8; w++) ss += red[w];
        inv[r] = 1.0f / ss;
    }
}

__global__ void attn_reduce(const float* __restrict__ part, const float* __restrict__ invsum,
                            fp16* __restrict__ attnp)
{
    int i = blockIdx.x * 256 + threadIdx.x;     // RQ*DIM
    int r = i >> 9;
    float s = 0.f;
#pragma unroll
    for (int z = 0; z < ASPLIT; z++) s += part[(size_t)z * RQ * DIM + i];
    attnp[i] = __float2half(s * invsum[r]);
}

__global__ void sigma_kernel(const float* __restrict__ h, const float* __restrict__ Wg2,
                             const float* __restrict__ bg2, float* __restrict__ sig)
{
    const int r = blockIdx.x;
    const int tid = threadIdx.x;
    float s = 0.f;
    for (int i = tid; i < DIM; i += 128)
        s = fmaf(h[(size_t)r * DIM + i], Wg2[i], s);
#pragma unroll
    for (int o = 16; o; o >>= 1) s += __shfl_xor_sync(0xffffffffu, s, o);
    __shared__ float red[4];
    if ((tid & 31) == 0) red[tid >> 5] = s;
    __syncthreads();
    if (tid == 0) {
        float t = red[0] + red[1] + red[2] + red[3] + bg2[0];
        sig[r] = 1.0f / (1.0f + __expf(-t));
    }
}

__global__ void final_kernel(const float* __restrict__ attn, const float* __restrict__ prev,
                             const float* __restrict__ sig, float* __restrict__ out)
{
    int i = blockIdx.x * 256 + threadIdx.x;
    int d = i & (DIM - 1);
    int t = i >> 9;
    int b = t & (BATCH - 1);
    int s = t >> 2;
    int r = b * SEQ + s;
    float g = sig[r];
    float a = attn[(size_t)r * DIM + d];
    float p = prev[i];
    out[i] = fmaf(a - p, g, p);
}

// ======================= launch =============================================
extern "C" void kernel_launch(void* const* d_in, const int* in_sizes, int n_in,
                              void* d_out, int out_size)
{
    (void)in_sizes; (void)n_in; (void)out_size;
    const float* q    = (const float*)d_in[0];
    const float* prev = (const float*)d_in[1];
    const float* Wq   = (const float*)d_in[2];
    const float* bq   = (const float*)d_in[3];
    const float* Wk   = (const float*)d_in[4];
    const float* bk   = (const float*)d_in[5];   (void)bk;  // cancels in softmax
    const float* Wv   = (const float*)d_in[6];
    const float* bv   = (const float*)d_in[7];
    const float* Wg1  = (const float*)d_in[8];
    const float* bg1  = (const float*)d_in[9];
    const float* Wg2  = (const float*)d_in[10];
    const float* bg2  = (const float*)d_in[11];
    const float* dk   = (const float*)d_in[12];
    const float* dv   = (const float*)d_in[13];
    float* out = (float*)d_out;

    cudaFuncSetAttribute(gemm_t<fp16>, cudaFuncAttributeMaxDynamicSharedMemorySize, GSMEM);
    cudaFuncSetAttribute(gemm_t<bf16>, cudaFuncAttributeMaxDynamicSharedMemorySize, GSMEM);

    fp16 *dkh, *qbh, *qh, *q2, *wqh, *wkt, *wvh, *g1h, *attnp, *cath;
    bf16 *dvt, *wb;
    float *hbuf, *attn, *inv, *sg, *part, *sp;
    cudaGetSymbolAddress((void**)&dkh, g_dkh);
    cudaGetSymbolAddress((void**)&dvt, g_dvt);
    cudaGetSymbolAddress((void**)&qbh, g_qbh);
    cudaGetSymbolAddress((void**)&qh,  g_qh);
    cudaGetSymbolAddress((void**)&q2,  g_q2);
    cudaGetSymbolAddress((void**)&wqh, g_wqh);
    cudaGetSymbolAddress((void**)&wkt, g_wkt);
    cudaGetSymbolAddress((void**)&wvh, g_wvh);
    cudaGetSymbolAddress((void**)&g1h, g_g1h);
    cudaGetSymbolAddress((void**)&wb,  g_wb);
    cudaGetSymbolAddress((void**)&sp,  g_sumpart);
    cudaGetSymbolAddress((void**)&attnp, g_attnp);
    cudaGetSymbolAddress((void**)&cath, g_cath);
    cudaGetSymbolAddress((void**)&hbuf, g_hbuf);
    cudaGetSymbolAddress((void**)&attn, g_attn);
    cudaGetSymbolAddress((void**)&inv, g_invsum);
    cudaGetSymbolAddress((void**)&sg,  g_sigma);
    cudaGetSymbolAddress((void**)&part, g_part);

    const float q_alpha = 0.08838834764831845f;   // D^-0.5 / TEMP

    // --- conversions / transposes ---
    cvt4<<<(NKV * DIM / 4) / 256, 256>>>((const float4*)dk, (__half2*)dkh, NKV * DIM / 4);
    tcvt<bf16><<<dim3(DIM / 32, NKV / 32), dim3(32, 8)>>>(dv, dvt, NKV, DIM);   // dv^T bf16
    cvt4<<<(DIM * DIM / 4) / 256, 256>>>((const float4*)Wq, (__half2*)wqh, DIM * DIM / 4);
    tcvt<fp16><<<dim3(DIM / 32, DIM / 32), dim3(32, 8)>>>(Wk, wkt, DIM, DIM);   // Wk^T fp16
    cvt4<<<(DIM * DIM / 4) / 256, 256>>>((const float4*)Wv, (__half2*)wvh, DIM * DIM / 4);
    cvt4<<<(DIM * 2 * DIM / 4) / 256, 256>>>((const float4*)Wg1, (__half2*)g1h, DIM * 2 * DIM / 4);
    prep_kernel<<<(SEQ * BATCH * DIM) / 256, 256>>>(q, prev, qbh, cath);

    // --- _q = qb @ Wq^T + bq -> fp16 ---
    gemm_t<fp16><<<dim3(DIM / 128, RQ / 128, 1), 256, GSMEM>>>(
        qbh, wqh, nullptr, qh,
        DIM, DIM, DIM, DIM, bq, 1, 1.f, 0, 0, 1, 0, nullptr);

    // --- q2 = (_q @ Wk) * alpha -> fp16  (B = Wk^T so A·B^T = _q @ Wk) ---
    gemm_t<fp16><<<dim3(DIM / 128, RQ / 128, 1), 256, GSMEM>>>(
        qh, wkt, nullptr, q2,
        DIM, DIM, DIM, DIM, nullptr, 0, q_alpha, 0, 0, 1, 0, nullptr);

    // --- logits+exp fused: wb = exp(q2 @ dk^T) bf16, + row partial sums ---
    gemm_t<fp16><<<dim3(RQ / 128, NKV / 128, 1), 256, GSMEM>>>(
        q2, dkh, nullptr, wb,
        DIM, DIM, NKV, DIM, nullptr, 0, 1.f, 0, 1, 3, 0, sp);

    reduce_inv<<<RQ, NSUM>>>(sp, inv);

    // --- split-K: part[z] = wb @ dvt^T over K-slices -> fp32 partials ---
    gemm_t<bf16><<<dim3(DIM / 128, RQ / 128, ASPLIT), 256, GSMEM>>>(
        wb, dvt, part, nullptr,
        NKV, NKV, DIM, AKSLICE, nullptr, 0, 1.f, 0, 0, 0, (long long)RQ * DIM, nullptr);

    // --- attnp = (w @ dv) * invsum -> fp16 ---
    attn_reduce<<<(RQ * DIM) / 256, 256>>>(part, inv, attnp);

    // --- attn = attnp @ Wv^T + bv -> fp32 g_attn + fp16 cath left half ---
    gemm_t<fp16><<<dim3(DIM / 128, RQ / 128, 1), 256, GSMEM>>>(
        attnp, wvh, attn, cath,
        DIM, DIM, DIM, DIM, bv, 1, 1.f, 0, 0, 4, (long long)(2 * DIM), nullptr);

    // --- gate: h = relu(cat @ Wg1^T + bg1) -> fp32 ---
    gemm_t<fp16><<<dim3(DIM / 128, RQ / 128, 1), 256, GSMEM>>>(
        cath, g1h, hbuf, nullptr,
        2 * DIM, 2 * DIM, DIM, 2 * DIM, bg1, 1, 1.f, 1, 0, 0, 0, nullptr);

    sigma_kernel<<<RQ, 128>>>(hbuf, Wg2, bg2, sg);
    final_kernel<<<(SEQ * BATCH * DIM) / 256, 256>>>(attn, prev, sg, out);
}

// round 8
// speedup vs baseline: 8.0103x; 1.0074x over previous
#include <cuda_runtime.h>
#include <cuda_fp16.h>
#include <cstdint>

#define SEQ   256
#define BATCH 4
#define DIM   512
#define NKV   32768
#define RQ    (SEQ * BATCH)          // 1024
#define ASPLIT 8
#define AKSLICE (NKV / ASPLIT)       // 4096
#define NSUM  (NKV / 128)            // 256

typedef unsigned int u32;
typedef __half fp16;

// ======================= device scratch ====================================
__device__ __align__(16) fp16 g_dkh[NKV * DIM];            // dk fp16
__device__ __align__(16) fp16 g_dvt[NKV * DIM];            // dv^T [DIM,NKV] fp16
__device__ __align__(16) fp16 g_qbh[RQ * DIM];
__device__ __align__(16) fp16 g_q2 [RQ * DIM];
__device__ __align__(16) fp16 g_wqt[DIM * DIM];            // Wq^T
__device__ __align__(16) fp16 g_wkt[DIM * DIM];            // Wk^T
__device__ __align__(16) fp16 g_wkq[DIM * DIM];            // α·Wk^T·Wq
__device__ __align__(16) fp16 g_wvh[DIM * DIM];
__device__ __align__(16) fp16 g_g1h[DIM * 2 * DIM];
__device__ __align__(16) float g_bias2[DIM];
__device__ __align__(16) fp16 g_wb[(size_t)RQ * NKV];      // exp weights fp16
__device__ __align__(16) float g_sumpart[(size_t)RQ * NSUM];
__device__ __align__(16) fp16 g_attnp[RQ * DIM];
__device__ __align__(16) fp16 g_cath[RQ * 2 * DIM];
__device__ __align__(16) float g_attn[RQ * DIM];
__device__ float g_invsum[RQ];
__device__ __align__(16) float g_part[(size_t)ASPLIT * RQ * DIM];  // shared split-K scratch

// ======================= PTX helpers =======================================
__device__ __forceinline__ u32 smem_u32(const void* p) {
    u32 a;
    asm("{ .reg .u64 t; cvta.to.shared.u64 t, %1; cvt.u32.u64 %0, t; }"
        : "=r"(a) : "l"(p));
    return a;
}

#define CP_ASYNC16(dst, src) \
    asm volatile("cp.async.cg.shared.global [%0], [%1], 16;" :: "r"(dst), "l"(src))
#define CP_COMMIT() asm volatile("cp.async.commit_group;" ::: "memory")
#define CP_WAIT(n)  asm volatile("cp.async.wait_group %0;" :: "n"(n) : "memory")

#define LDMX4(r, addr) \
    asm volatile("ldmatrix.sync.aligned.m8n8.x4.shared.b16 {%0,%1,%2,%3}, [%4];" \
        : "=r"((r)[0]), "=r"((r)[1]), "=r"((r)[2]), "=r"((r)[3]) : "r"(addr))

#define MMA_F16(d, a, b) \
    asm volatile("mma.sync.aligned.m16n8k16.row.col.f32.f16.f16.f32 " \
        "{%0,%1,%2,%3}, {%4,%5,%6,%7}, {%8,%9}, {%0,%1,%2,%3};" \
        : "+f"((d)[0]), "+f"((d)[1]), "+f"((d)[2]), "+f"((d)[3]) \
        : "r"((a)[0]), "r"((a)[1]), "r"((a)[2]), "r"((a)[3]), \
          "r"((b)[0]), "r"((b)[1]))

__device__ __forceinline__ float fast_exp(float x) {
    float t = x * 1.4426950408889634f;
    t = fmaxf(t, -125.0f);
    float fi = floorf(t);
    float f = t - fi;
    float p = 1.5403530393381608e-4f;
    p = fmaf(p, f, 1.3333558146428443e-3f);
    p = fmaf(p, f, 9.618129107628477e-3f);
    p = fmaf(p, f, 5.550410866482158e-2f);
    p = fmaf(p, f, 2.402265069591007e-1f);
    p = fmaf(p, f, 6.931471805599453e-1f);
    p = fmaf(p, f, 1.0f);
    return p * __int_as_float(((int)fi + 127) << 23);
}

// ======================= pipelined HMMA fp16 GEMM ==========================
// C[M,N] = A[M,K] * B[N,K]^T, fp32 accumulate
// out_mode: 0 fp32 partials (z*strideZ, alpha applied, bias ignored);
//           1 fp16; 3 exp(acc)->fp16 + per-(row,ntile) partial sums
// bias_mode: 0 none, 1 per-col bias[n]
#define GKC 64
#define SROW 144
#define TILE_B (128 * SROW)
#define STG_B (2 * TILE_B)
#define GSMEM (3 * STG_B)

__global__ __launch_bounds__(256, 2)
void gemm_f16(const fp16* __restrict__ A, const fp16* __restrict__ B,
              float* __restrict__ Cf, fp16* __restrict__ Ch,
              int lda, int ldb, int ldc, int kslice,
              const float* __restrict__ bias, int bias_mode,
              float alpha, int swap, int out_mode,
              long long strideZ, float* __restrict__ sums)
{
    extern __shared__ char smem[];
    const u32 sb = smem_u32(smem);
    const int tid = threadIdx.x;
    const int lane = tid & 31, wid = tid >> 5;
    const int wm = wid >> 1, wn = wid & 1;
    const int mtile = swap ? blockIdx.x : blockIdx.y;
    const int ntile = swap ? blockIdx.y : blockIdx.x;
    const int z = blockIdx.z;
    const long long kbase = (long long)z * kslice;
    const int NC = kslice / GKC;

    auto load_stage = [&](int c) {
        const u32 st = sb + (u32)(c % 3) * STG_B;
        const long long kb = kbase + (long long)c * GKC;
#pragma unroll
        for (int i = 0; i < 4; i++) {
            const int idx = tid + i * 256;
            const int row = idx >> 3, ch = idx & 7;
            const u32 so = (u32)(row * SROW + ch * 16);
            const long long aoff = (long long)(mtile * 128 + row) * lda + kb + ch * 8;
            CP_ASYNC16(st + so, (const char*)(A + aoff));
        }
#pragma unroll
        for (int i = 0; i < 4; i++) {
            const int idx = tid + i * 256;
            const int row = idx >> 3, ch = idx & 7;
            const u32 so = (u32)(row * SROW + ch * 16);
            const long long boff = (long long)(ntile * 128 + row) * ldb + kb + ch * 8;
            CP_ASYNC16(st + TILE_B + so, (const char*)(B + boff));
        }
        CP_COMMIT();
    };

    float acc[2][8][4];
#pragma unroll
    for (int mt = 0; mt < 2; mt++)
#pragma unroll
        for (int nt = 0; nt < 8; nt++)
#pragma unroll
            for (int j = 0; j < 4; j++) acc[mt][nt][j] = 0.f;

    load_stage(0);
    if (NC > 1) load_stage(1);

    const u32 a_row = (u32)(wm * 32 + (lane & 15));
    const u32 a_ke  = (u32)((lane >> 4) * 8);
    const u32 b_row = (u32)(wn * 64 + ((lane >> 4) << 3) + (lane & 7));
    const u32 b_ke  = (u32)(((lane >> 3) & 1) * 8);

    for (int c = 0; c < NC; c++) {
        if (c + 1 < NC) { CP_WAIT(1); } else { CP_WAIT(0); }
        __syncthreads();
        if (c + 2 < NC) load_stage(c + 2);

        const u32 st = sb + (u32)(c % 3) * STG_B;
#pragma unroll
        for (int ks = 0; ks < 4; ks++) {
            const u32 k0 = ks * 16;
            u32 af[2][4], bfr[8][2];
#pragma unroll
            for (int mt = 0; mt < 2; mt++) {
                const u32 addr = st + (a_row + mt * 16) * SROW + (k0 + a_ke) * 2;
                LDMX4(af[mt], addr);
            }
#pragma unroll
            for (int nt2 = 0; nt2 < 4; nt2++) {
                const u32 addr = st + TILE_B + (b_row + nt2 * 16) * SROW + (k0 + b_ke) * 2;
                u32 r[4];
                LDMX4(r, addr);
                bfr[2 * nt2][0] = r[0]; bfr[2 * nt2][1] = r[1];
                bfr[2 * nt2 + 1][0] = r[2]; bfr[2 * nt2 + 1][1] = r[3];
            }
#pragma unroll
            for (int mt = 0; mt < 2; mt++)
#pragma unroll
                for (int nt = 0; nt < 8; nt++)
                    MMA_F16(acc[mt][nt], af[mt], bfr[nt]);
        }
    }
    __syncthreads();

    // ---------------- epilogue: stage fp32 tile in smem --------------------
    float* stage = (float*)smem;                    // [128][132]
    const int l4 = lane >> 2, l2 = (lane & 3) * 2;

#pragma unroll
    for (int mt = 0; mt < 2; mt++) {
        const int lr = wm * 32 + mt * 16 + l4;
#pragma unroll
        for (int nt = 0; nt < 8; nt++) {
            const int lc = wn * 64 + nt * 8 + l2;
            float v0, v1, v2, v3;
            if (out_mode == 3) {
                v0 = fast_exp(acc[mt][nt][0]);
                v1 = fast_exp(acc[mt][nt][1]);
                v2 = fast_exp(acc[mt][nt][2]);
                v3 = fast_exp(acc[mt][nt][3]);
            } else {
                float bc0 = 0.f, bc1 = 0.f;
                if (bias_mode == 1) {
                    bc0 = bias[ntile * 128 + lc];
                    bc1 = bias[ntile * 128 + lc + 1];
                }
                v0 = (acc[mt][nt][0] + bc0) * alpha;
                v1 = (acc[mt][nt][1] + bc1) * alpha;
                v2 = (acc[mt][nt][2] + bc0) * alpha;
                v3 = (acc[mt][nt][3] + bc1) * alpha;
            }
            stage[lr * 132 + lc] = v0;
            stage[lr * 132 + lc + 1] = v1;
            stage[(lr + 8) * 132 + lc] = v2;
            stage[(lr + 8) * 132 + lc + 1] = v3;
        }
    }
    __syncthreads();

    if (out_mode == 0) {
        float* Cp = Cf + (long long)z * strideZ
                  + (long long)(mtile * 128) * ldc + ntile * 128;
#pragma unroll
        for (int i = 0; i < 16; i++) {
            const int idx = tid + i * 256;
            const int rr = idx >> 5, c4 = (idx & 31) * 4;
            float4 v = *(float4*)&stage[rr * 132 + c4];
            *(float4*)(Cp + (long long)rr * ldc + c4) = v;
        }
    } else {
        fp16* Hp = Ch + (long long)(mtile * 128) * ldc + ntile * 128;
#pragma unroll
        for (int i = 0; i < 16; i++) {
            const int idx = tid + i * 256;
            const int rr = idx >> 5, c4 = (idx & 31) * 4;
            float4 v = *(float4*)&stage[rr * 132 + c4];
            __half2* hq = (__half2*)(Hp + (long long)rr * ldc + c4);
            hq[0] = __floats2half2_rn(v.x, v.y);
            hq[1] = __floats2half2_rn(v.z, v.w);
        }
        if (out_mode == 3) {
            const int r = tid >> 1, h = tid & 1;
            float s = 0.f;
            const float* rp = &stage[r * 132 + h * 64];
#pragma unroll
            for (int j = 0; j < 64; j++) s += rp[j];
            s += __shfl_xor_sync(0xffffffffu, s, 1);
            if (h == 0)
                sums[(size_t)(mtile * 128 + r) * NSUM + ntile] = s;
        }
    }
}

// ======================= elementwise / reduce kernels =======================
__global__ void cvt4(const float4* __restrict__ x, __half2* __restrict__ h, int n4)
{
    int i = blockIdx.x * 256 + threadIdx.x;
    if (i >= n4) return;
    float4 v = x[i];
    h[2 * i]     = __floats2half2_rn(v.x, v.y);
    h[2 * i + 1] = __floats2half2_rn(v.z, v.w);
}

// combined Wv + Wg1 convert
__global__ void wcvt(const float4* __restrict__ wv, __half2* __restrict__ wvh,
                     const float4* __restrict__ wg1, __half2* __restrict__ g1h)
{
    int i = blockIdx.x * 256 + threadIdx.x;
    if (i < 65536) {
        float4 v = wv[i];
        wvh[2 * i]     = __floats2half2_rn(v.x, v.y);
        wvh[2 * i + 1] = __floats2half2_rn(v.z, v.w);
    } else {
        int j = i - 65536;                 // < 131072
        float4 v = wg1[j];
        g1h[2 * j]     = __floats2half2_rn(v.x, v.y);
        g1h[2 * j + 1] = __floats2half2_rn(v.z, v.w);
    }
}

// transpose+convert dv [NKV,DIM] -> dvt [DIM,NKV] fp16
__global__ void tcvt_dv(const float* __restrict__ src, fp16* __restrict__ dst)
{
    __shared__ float tile[32][33];
    const int c0 = blockIdx.x * 32, r0 = blockIdx.y * 32;
    const int tx = threadIdx.x, ty = threadIdx.y;
#pragma unroll
    for (int i = 0; i < 32; i += 8)
        tile[ty + i][tx] = src[(size_t)(r0 + ty + i) * DIM + c0 + tx];
    __syncthreads();
#pragma unroll
    for (int i = 0; i < 32; i += 8)
        dst[(size_t)(c0 + ty + i) * NKV + r0 + tx] = __float2half(tile[tx][ty + i]);
}

// transpose+convert Wq->wqt and Wk->wkt (z selects)
__global__ void ttcvt2(const float* __restrict__ wq, fp16* __restrict__ wqt,
                       const float* __restrict__ wk, fp16* __restrict__ wkt)
{
    __shared__ float tile[32][33];
    const float* src = blockIdx.z ? wk : wq;
    fp16* dst = blockIdx.z ? wkt : wqt;
    const int c0 = blockIdx.x * 32, r0 = blockIdx.y * 32;
    const int tx = threadIdx.x, ty = threadIdx.y;
#pragma unroll
    for (int i = 0; i < 32; i += 8)
        tile[ty + i][tx] = src[(size_t)(r0 + ty + i) * DIM + c0 + tx];
    __syncthreads();
#pragma unroll
    for (int i = 0; i < 32; i += 8)
        dst[(size_t)(c0 + ty + i) * DIM + r0 + tx] = __float2half(tile[tx][ty + i]);
}

__global__ void prep_kernel(const float* __restrict__ q, const float* __restrict__ prev,
                            fp16* __restrict__ qbh, fp16* __restrict__ cath)
{
    int i = blockIdx.x * 256 + threadIdx.x;
    int d = i & (DIM - 1);
    int t = i >> 9;
    int b = t & (BATCH - 1);
    int s = t >> 2;
    int r = b * SEQ + s;
    qbh[(size_t)r * DIM + d] = __float2half(q[i]);
    cath[(size_t)r * 2 * DIM + DIM + d] = __float2half(prev[i]);
}

// bias2[j] = alpha * sum_k bq[k] * Wk[k,j]
__global__ void bias2_kernel(const float* __restrict__ bq, const float* __restrict__ Wk,
                             float* __restrict__ bias2, float alpha)
{
    int j = blockIdx.x * 256 + threadIdx.x;    // < 512
    float s = 0.f;
    for (int k = 0; k < DIM; k++)
        s = fmaf(bq[k], Wk[(size_t)k * DIM + j], s);
    bias2[j] = s * alpha;
}

// generic split-K reduce -> fp16 (+optional per-col bias, col = i & 511)
__global__ void red16(const float* __restrict__ part, int zc, long long stride,
                      const float* __restrict__ bias, fp16* __restrict__ out, int n)
{
    int i = blockIdx.x * 256 + threadIdx.x;
    if (i >= n) return;
    float s = 0.f;
    for (int z = 0; z < zc; z++) s += part[(long long)z * stride + i];
    if (bias) s += bias[i & (DIM - 1)];
    out[i] = __float2half(s);
}

__global__ void reduce_inv(const float* __restrict__ sp, float* __restrict__ inv)
{
    const int r = blockIdx.x;
    const int t = threadIdx.x;
    __shared__ float red[8];
    float s = sp[(size_t)r * NSUM + t];
#pragma unroll
    for (int o = 16; o; o >>= 1) s += __shfl_xor_sync(0xffffffffu, s, o);
    if ((t & 31) == 0) red[t >> 5] = s;
    __syncthreads();
    if (t == 0) {
        float ss = 0.f;
        for (int w = 0; w < 8; w++) ss += red[w];
        inv[r] = 1.0f / ss;
    }
}

__global__ void attn_reduce(const float* __restrict__ part, const float* __restrict__ invsum,
                            fp16* __restrict__ attnp)
{
    int i = blockIdx.x * 256 + threadIdx.x;     // RQ*DIM
    int r = i >> 9;
    float s = 0.f;
#pragma unroll
    for (int z = 0; z < ASPLIT; z++) s += part[(size_t)z * RQ * DIM + i];
    attnp[i] = __float2half(s * invsum[r]);
}

// attnfinal reduce: attn = Σ4 part + bv -> fp32 attn + fp16 cath left half
__global__ void red_af(const float* __restrict__ part, const float* __restrict__ bv,
                       float* __restrict__ attn, fp16* __restrict__ cath)
{
    int i = blockIdx.x * 256 + threadIdx.x;     // RQ*DIM
    int r = i >> 9, d = i & (DIM - 1);
    float s = 0.f;
#pragma unroll
    for (int z = 0; z < 4; z++) s += part[(size_t)z * RQ * DIM + i];
    s += bv[d];
    attn[i] = s;
    cath[(size_t)r * 2 * DIM + d] = __float2half(s);
}

// fused: gate split-K reduce + relu + sigma dot + sigmoid + final blend
__global__ void gate_sigma_final(const float* __restrict__ partg, const float* __restrict__ bg1,
                                 const float* __restrict__ Wg2, const float* __restrict__ bg2,
                                 const float* __restrict__ attn, const float* __restrict__ prev,
                                 float* __restrict__ out)
{
    const int r = blockIdx.x;                   // 0..RQ-1
    const int tid = threadIdx.x;                // 128
    float s = 0.f;
    for (int d = tid; d < DIM; d += 128) {
        float v = 0.f;
#pragma unroll
        for (int z = 0; z < 8; z++)
            v += partg[(size_t)z * RQ * DIM + (size_t)r * DIM + d];
        v = fmaxf(v + bg1[d], 0.f);
        s = fmaf(v, Wg2[d], s);
    }
#pragma unroll
    for (int o = 16; o; o >>= 1) s += __shfl_xor_sync(0xffffffffu, s, o);
    __shared__ float red[4];
    __shared__ float gsh;
    if ((tid & 31) == 0) red[tid >> 5] = s;
    __syncthreads();
    if (tid == 0) {
        float t = red[0] + red[1] + red[2] + red[3] + bg2[0];
        gsh = 1.0f / (1.0f + __expf(-t));
    }
    __syncthreads();
    const float g = gsh;
    const int b = r / SEQ, sq = r % SEQ;
    for (int d = tid; d < DIM; d += 128) {
        const int oi = (sq * BATCH + b) * DIM + d;
        float a = attn[(size_t)r * DIM + d];
        float p = prev[oi];
        out[oi] = fmaf(a - p, g, p);
    }
}

// ======================= launch =============================================
extern "C" void kernel_launch(void* const* d_in, const int* in_sizes, int n_in,
                              void* d_out, int out_size)
{
    (void)in_sizes; (void)n_in; (void)out_size;
    const float* q    = (const float*)d_in[0];
    const float* prev = (const float*)d_in[1];
    const float* Wq   = (const float*)d_in[2];
    const float* bq   = (const float*)d_in[3];
    const float* Wk   = (const float*)d_in[4];
    const float* bk   = (const float*)d_in[5];   (void)bk;  // cancels in softmax
    const float* Wv   = (const float*)d_in[6];
    const float* bv   = (const float*)d_in[7];
    const float* Wg1  = (const float*)d_in[8];
    const float* bg1  = (const float*)d_in[9];
    const float* Wg2  = (const float*)d_in[10];
    const float* bg2  = (const float*)d_in[11];
    const float* dk   = (const float*)d_in[12];
    const float* dv   = (const float*)d_in[13];
    float* out = (float*)d_out;

    cudaFuncSetAttribute(gemm_f16, cudaFuncAttributeMaxDynamicSharedMemorySize, GSMEM);

    fp16 *dkh, *dvt, *qbh, *q2, *wqt, *wkt, *wkq, *wvh, *g1h, *wb, *attnp, *cath;
    float *attn, *inv, *part, *sp, *bias2;
    cudaGetSymbolAddress((void**)&dkh, g_dkh);
    cudaGetSymbolAddress((void**)&dvt, g_dvt);
    cudaGetSymbolAddress((void**)&qbh, g_qbh);
    cudaGetSymbolAddress((void**)&q2,  g_q2);
    cudaGetSymbolAddress((void**)&wqt, g_wqt);
    cudaGetSymbolAddress((void**)&wkt, g_wkt);
    cudaGetSymbolAddress((void**)&wkq, g_wkq);
    cudaGetSymbolAddress((void**)&wvh, g_wvh);
    cudaGetSymbolAddress((void**)&g1h, g_g1h);
    cudaGetSymbolAddress((void**)&wb,  g_wb);
    cudaGetSymbolAddress((void**)&sp,  g_sumpart);
    cudaGetSymbolAddress((void**)&attnp, g_attnp);
    cudaGetSymbolAddress((void**)&cath, g_cath);
    cudaGetSymbolAddress((void**)&attn, g_attn);
    cudaGetSymbolAddress((void**)&inv, g_invsum);
    cudaGetSymbolAddress((void**)&part, g_part);
    cudaGetSymbolAddress((void**)&bias2, g_bias2);

    const float q_alpha = 0.08838834764831845f;   // D^-0.5 / TEMP

    // --- conversions / prep ---
    cvt4<<<(NKV * DIM / 4) / 256, 256>>>((const float4*)dk, (__half2*)dkh, NKV * DIM / 4);
    tcvt_dv<<<dim3(DIM / 32, NKV / 32), dim3(32, 8)>>>(dv, dvt);
    ttcvt2<<<dim3(DIM / 32, DIM / 32, 2), dim3(32, 8)>>>(Wq, wqt, Wk, wkt);
    wcvt<<<768, 256>>>((const float4*)Wv, (__half2*)wvh, (const float4*)Wg1, (__half2*)g1h);
    prep_kernel<<<(SEQ * BATCH * DIM) / 256, 256>>>(q, prev, qbh, cath);
    bias2_kernel<<<2, 256>>>(bq, Wk, bias2, q_alpha);

    // --- Wkq = α·(Wk^T · Wq) : C[i,j] = Σ wkt[i,k]·wqt[j,k], split-K z=4 ---
    gemm_f16<<<dim3(4, 4, 4), 256, GSMEM>>>(
        wkt, wqt, part, nullptr,
        DIM, DIM, DIM, 128, nullptr, 0, q_alpha, 0, 0, (long long)DIM * DIM, nullptr);
    red16<<<(DIM * DIM) / 256, 256>>>(part, 4, (long long)DIM * DIM, nullptr, wkq, DIM * DIM);

    // --- q2 = qb @ Wkq^T + bias2, split-K z=4 ---
    gemm_f16<<<dim3(4, 8, 4), 256, GSMEM>>>(
        qbh, wkq, part, nullptr,
        DIM, DIM, DIM, 128, nullptr, 0, 1.f, 0, 0, (long long)RQ * DIM, nullptr);
    red16<<<(RQ * DIM) / 256, 256>>>(part, 4, (long long)RQ * DIM, bias2, q2, RQ * DIM);

    // --- logits+exp fused: wb = exp(q2 @ dk^T) fp16 + row partial sums ---
    gemm_f16<<<dim3(RQ / 128, NKV / 128, 1), 256, GSMEM>>>(
        q2, dkh, nullptr, wb,
        DIM, DIM, NKV, DIM, nullptr, 0, 1.f, 1, 3, 0, sp);

    reduce_inv<<<RQ, NSUM>>>(sp, inv);

    // --- attn split-K: part[z] = wb @ dvt^T, z=8 ---
    gemm_f16<<<dim3(DIM / 128, RQ / 128, ASPLIT), 256, GSMEM>>>(
        wb, dvt, part, nullptr,
        NKV, NKV, DIM, AKSLICE, nullptr, 0, 1.f, 0, 0, (long long)RQ * DIM, nullptr);
    attn_reduce<<<(RQ * DIM) / 256, 256>>>(part, inv, attnp);

    // --- attn = attnp @ Wv^T + bv, split-K z=4 ---
    gemm_f16<<<dim3(4, 8, 4), 256, GSMEM>>>(
        attnp, wvh, part, nullptr,
        DIM, DIM, DIM, 128, nullptr, 0, 1.f, 0, 0, (long long)RQ * DIM, nullptr);
    red_af<<<(RQ * DIM) / 256, 256>>>(part, bv, attn, cath);

    // --- gate GEMM: partg[z] = cat @ Wg1^T slices, z=8 (K=1024) ---
    gemm_f16<<<dim3(4, 8, 8), 256, GSMEM>>>(
        cath, g1h, part, nullptr,
        2 * DIM, 2 * DIM, DIM, 128, nullptr, 0, 1.f, 0, 0, (long long)RQ * DIM, nullptr);

    // --- fused gate-reduce + relu + sigma + final blend ---
    gate_sigma_final<<<RQ, 128>>>(part, bg1, Wg2, bg2, attn, prev, out);
}